// round 1
// baseline (speedup 1.0000x reference)
#include <cuda_runtime.h>
#include <math_constants.h>

#define B_   2
#define L_   2048
#define E_   1024
#define H_   16
#define D_   64
#define DFF_ 4096
#define M_   (B_ * L_)   // 4096 tokens

// ---------------- scratch (device globals: allocation-guard safe) ----------------
__device__ float g_h[M_ * E_];                       // rmsnorm outputs (reused)
__device__ float g_qkv[(size_t)M_ * 3 * H_ * D_];    // QKV projections
__device__ float g_ctx[M_ * H_ * D_];                // attention context
__device__ float g_x[M_ * E_];                       // running residual stream
__device__ float g_gate[(size_t)M_ * DFF_];          // gelu branch
__device__ float g_val[(size_t)M_ * DFF_];           // value branch

// ---------------- rmsnorm: y = x / sqrt(mean(x^2)) ----------------
__global__ __launch_bounds__(256) void rmsnorm_kernel(const float* __restrict__ x,
                                                      float* __restrict__ y) {
    int row = blockIdx.x;
    float4 a = ((const float4*)(x + (size_t)row * E_))[threadIdx.x];
    float ss = a.x * a.x + a.y * a.y + a.z * a.z + a.w * a.w;
    __shared__ float red[8];
    __shared__ float sinv;
#pragma unroll
    for (int o = 16; o > 0; o >>= 1) ss += __shfl_xor_sync(0xffffffffu, ss, o);
    if ((threadIdx.x & 31) == 0) red[threadIdx.x >> 5] = ss;
    __syncthreads();
    if (threadIdx.x == 0) {
        float t = 0.f;
#pragma unroll
        for (int i = 0; i < 8; i++) t += red[i];
        sinv = rsqrtf(t * (1.0f / E_));
    }
    __syncthreads();
    float c = sinv;
    float4 o = make_float4(a.x * c, a.y * c, a.z * c, a.w * c);
    ((float4*)(y + (size_t)row * E_))[threadIdx.x] = o;
}

// ---------------- fused: x = x + rmsnorm(x);  h = rmsnorm(x) ----------------
__global__ __launch_bounds__(256) void addnorm_kernel(float* __restrict__ x,
                                                      float* __restrict__ h) {
    int row = blockIdx.x;
    float4 a = ((const float4*)(x + (size_t)row * E_))[threadIdx.x];
    __shared__ float red[8];
    __shared__ float sval;
    // pass 1: rms of x
    float ss = a.x * a.x + a.y * a.y + a.z * a.z + a.w * a.w;
#pragma unroll
    for (int o = 16; o > 0; o >>= 1) ss += __shfl_xor_sync(0xffffffffu, ss, o);
    if ((threadIdx.x & 31) == 0) red[threadIdx.x >> 5] = ss;
    __syncthreads();
    if (threadIdx.x == 0) {
        float t = 0.f;
#pragma unroll
        for (int i = 0; i < 8; i++) t += red[i];
        sval = 1.0f + rsqrtf(t * (1.0f / E_));   // x2 = x * (1 + 1/rms)
    }
    __syncthreads();
    float c = sval;
    a.x *= c; a.y *= c; a.z *= c; a.w *= c;
    // pass 2: rms of x2
    float ss2 = a.x * a.x + a.y * a.y + a.z * a.z + a.w * a.w;
#pragma unroll
    for (int o = 16; o > 0; o >>= 1) ss2 += __shfl_xor_sync(0xffffffffu, ss2, o);
    if ((threadIdx.x & 31) == 0) red[threadIdx.x >> 5] = ss2;
    __syncthreads();
    if (threadIdx.x == 0) {
        float t = 0.f;
#pragma unroll
        for (int i = 0; i < 8; i++) t += red[i];
        sval = rsqrtf(t * (1.0f / E_));
    }
    __syncthreads();
    float inv2 = sval;
    ((float4*)(x + (size_t)row * E_))[threadIdx.x] = a;
    float4 o = make_float4(a.x * inv2, a.y * inv2, a.z * inv2, a.w * inv2);
    ((float4*)(h + (size_t)row * E_))[threadIdx.x] = o;
}

// ---------------- geglu: g = gelu_exact(g) * v ----------------
__global__ __launch_bounds__(256) void geglu_kernel(float* __restrict__ g,
                                                    const float* __restrict__ v) {
    int i = blockIdx.x * 256 + threadIdx.x;
    float x = g[i];
    float gel = 0.5f * x * (1.0f + erff(x * 0.70710678118654752f));
    g[i] = gel * v[i];
}

// ---------------- SGEMM: C = A(MxK) @ B(KxN) [+ bias] [+ res] ----------------
// 128x128 tile, BK=8, 8x8 per thread, 256 threads. All dims multiples of 128/8.
__global__ __launch_bounds__(256) void sgemm_kernel(
    int M, int N, int K,
    const float* __restrict__ A, const float* __restrict__ B,
    const float* __restrict__ bias, const float* __restrict__ res,
    float* __restrict__ C) {
    __shared__ float As[8][128];
    __shared__ float Bs[8][128];
    const int tid  = threadIdx.x;
    const int bm   = blockIdx.y * 128;
    const int bn   = blockIdx.x * 128;
    const int trow = (tid >> 4) * 8;
    const int tcol = (tid & 15) * 8;
    const int a_row = tid >> 1;
    const int a_col = (tid & 1) * 4;
    const int b_row = tid >> 5;
    const int b_col = (tid & 31) * 4;
    const float* Aptr = A + (size_t)(bm + a_row) * K + a_col;
    const float* Bptr = B + (size_t)b_row * N + bn + b_col;

    float acc[8][8];
#pragma unroll
    for (int i = 0; i < 8; i++)
#pragma unroll
        for (int j = 0; j < 8; j++) acc[i][j] = 0.f;

#pragma unroll 1
    for (int k0 = 0; k0 < K; k0 += 8) {
        float4 av = *(const float4*)(Aptr + k0);
        As[a_col + 0][a_row] = av.x;
        As[a_col + 1][a_row] = av.y;
        As[a_col + 2][a_row] = av.z;
        As[a_col + 3][a_row] = av.w;
        *(float4*)&Bs[b_row][b_col] = *(const float4*)(Bptr + (size_t)k0 * N);
        __syncthreads();
#pragma unroll
        for (int kk = 0; kk < 8; kk++) {
            float ar[8], br[8];
            *(float4*)&ar[0] = *(const float4*)&As[kk][trow];
            *(float4*)&ar[4] = *(const float4*)&As[kk][trow + 4];
            *(float4*)&br[0] = *(const float4*)&Bs[kk][tcol];
            *(float4*)&br[4] = *(const float4*)&Bs[kk][tcol + 4];
#pragma unroll
            for (int i = 0; i < 8; i++)
#pragma unroll
                for (int j = 0; j < 8; j++) acc[i][j] += ar[i] * br[j];
        }
        __syncthreads();
    }

#pragma unroll
    for (int i = 0; i < 8; i++) {
        size_t r = (size_t)(bm + trow + i);
#pragma unroll
        for (int j = 0; j < 8; j += 4) {
            int c = bn + tcol + j;
            float4 o = make_float4(acc[i][j], acc[i][j + 1], acc[i][j + 2], acc[i][j + 3]);
            if (bias) {
                o.x += bias[c]; o.y += bias[c + 1]; o.z += bias[c + 2]; o.w += bias[c + 3];
            }
            if (res) {
                float4 rv = *(const float4*)(res + r * N + c);
                o.x += rv.x; o.y += rv.y; o.z += rv.z; o.w += rv.w;
            }
            *(float4*)(C + r * N + c) = o;
        }
    }
}

// ---------------- flash attention with ALiBi + causal ----------------
// qkv layout: [b][l][h][s][d], s in {q,k,v}. ctx layout: [b][l][h*D+d].
// 64-query tile per block, 64-key tiles, fp32, online softmax, 1/8 folded into Q.
#define ATT_PAD 68
#define ATT_SMEM ((4 * 64 * ATT_PAD + 3 * 64) * 4)

__global__ __launch_bounds__(256) void attn_kernel(const float* __restrict__ qkv,
                                                   float* __restrict__ ctx) {
    extern __shared__ float sm[];
    float* Qs  = sm;
    float* Ks  = Qs + 64 * ATT_PAD;
    float* Vs  = Ks + 64 * ATT_PAD;
    float* Ps  = Vs + 64 * ATT_PAD;
    float* m_s = Ps + 64 * ATT_PAD;
    float* l_s = m_s + 64;
    float* a_s = l_s + 64;

    const int qt = blockIdx.x, h = blockIdx.y, b = blockIdx.z;
    const int m0 = qt * 64;
    const int tid = threadIdx.x;
    const float slope = exp2f(-(1.0f + 7.0f * (float)h / 15.0f));

    // load + pre-scale Q tile
    for (int i = tid; i < 64 * 16; i += 256) {
        int r = i >> 4, c = (i & 15) << 2;
        float4 v = *(const float4*)(qkv + ((((size_t)(b * L_ + m0 + r) * H_ + h) * 3 + 0) * D_ + c));
        Qs[r * ATT_PAD + c + 0] = v.x * 0.125f;
        Qs[r * ATT_PAD + c + 1] = v.y * 0.125f;
        Qs[r * ATT_PAD + c + 2] = v.z * 0.125f;
        Qs[r * ATT_PAD + c + 3] = v.w * 0.125f;
    }
    if (tid < 64) { m_s[tid] = -CUDART_INF_F; l_s[tid] = 0.f; }

    float acc[4][4];
#pragma unroll
    for (int i = 0; i < 4; i++)
#pragma unroll
        for (int j = 0; j < 4; j++) acc[i][j] = 0.f;

    const int tx = tid & 15, ty = tid >> 4;
    const int row0 = ty * 4, col0 = tx * 4;
    const int warp = tid >> 5, lane = tid & 31;

    for (int kt = 0; kt <= qt; kt++) {
        const int n0 = kt * 64;
        __syncthreads();
        for (int i = tid; i < 64 * 16; i += 256) {
            int r = i >> 4, c = (i & 15) << 2;
            size_t base = ((size_t)(b * L_ + n0 + r) * H_ + h) * 3;
            float4 kv = *(const float4*)(qkv + (base + 1) * D_ + c);
            float4 vv = *(const float4*)(qkv + (base + 2) * D_ + c);
            Ks[r * ATT_PAD + c + 0] = kv.x; Ks[r * ATT_PAD + c + 1] = kv.y;
            Ks[r * ATT_PAD + c + 2] = kv.z; Ks[r * ATT_PAD + c + 3] = kv.w;
            Vs[r * ATT_PAD + c + 0] = vv.x; Vs[r * ATT_PAD + c + 1] = vv.y;
            Vs[r * ATT_PAD + c + 2] = vv.z; Vs[r * ATT_PAD + c + 3] = vv.w;
        }
        __syncthreads();

        // S = (Q/8) K^T
        float s[4][4];
#pragma unroll
        for (int i = 0; i < 4; i++)
#pragma unroll
            for (int j = 0; j < 4; j++) s[i][j] = 0.f;
#pragma unroll
        for (int d = 0; d < 64; d += 4) {
            float qa[4][4], kb[4][4];
#pragma unroll
            for (int i = 0; i < 4; i++) {
                float4 t = *(const float4*)&Qs[(row0 + i) * ATT_PAD + d];
                qa[i][0] = t.x; qa[i][1] = t.y; qa[i][2] = t.z; qa[i][3] = t.w;
            }
#pragma unroll
            for (int j = 0; j < 4; j++) {
                float4 t = *(const float4*)&Ks[(col0 + j) * ATT_PAD + d];
                kb[j][0] = t.x; kb[j][1] = t.y; kb[j][2] = t.z; kb[j][3] = t.w;
            }
#pragma unroll
            for (int dd = 0; dd < 4; dd++)
#pragma unroll
                for (int i = 0; i < 4; i++)
#pragma unroll
                    for (int j = 0; j < 4; j++) s[i][j] += qa[i][dd] * kb[j][dd];
        }
        // alibi + causal mask, write scores to Ps
#pragma unroll
        for (int i = 0; i < 4; i++)
#pragma unroll
            for (int j = 0; j < 4; j++) {
                int gi = m0 + row0 + i, gj = n0 + col0 + j;
                float v = s[i][j] + slope * (float)(gj - gi);
                if (gj > gi) v = -CUDART_INF_F;
                Ps[(row0 + i) * ATT_PAD + col0 + j] = v;
            }
        __syncthreads();

        // online softmax: warp w owns rows w*8..w*8+7
#pragma unroll
        for (int rr = 0; rr < 8; rr++) {
            int r = warp * 8 + rr;
            float v0 = Ps[r * ATT_PAD + lane];
            float v1 = Ps[r * ATT_PAD + 32 + lane];
            float mx = fmaxf(v0, v1);
#pragma unroll
            for (int o = 16; o > 0; o >>= 1) mx = fmaxf(mx, __shfl_xor_sync(0xffffffffu, mx, o));
            float mo = m_s[r];
            float mn = fmaxf(mo, mx);
            float p0 = __expf(v0 - mn);
            float p1 = __expf(v1 - mn);
            float sum = p0 + p1;
#pragma unroll
            for (int o = 16; o > 0; o >>= 1) sum += __shfl_xor_sync(0xffffffffu, sum, o);
            Ps[r * ATT_PAD + lane] = p0;
            Ps[r * ATT_PAD + 32 + lane] = p1;
            if (lane == 0) {
                float al = __expf(mo - mn);
                l_s[r] = l_s[r] * al + sum;
                m_s[r] = mn;
                a_s[r] = al;
            }
        }
        __syncthreads();

        // rescale accumulator, then O += P @ V
        float al[4];
#pragma unroll
        for (int i = 0; i < 4; i++) al[i] = a_s[row0 + i];
#pragma unroll
        for (int i = 0; i < 4; i++)
#pragma unroll
            for (int j = 0; j < 4; j++) acc[i][j] *= al[i];
#pragma unroll
        for (int j = 0; j < 64; j += 4) {
            float pr[4][4];
#pragma unroll
            for (int i = 0; i < 4; i++) {
                float4 t = *(const float4*)&Ps[(row0 + i) * ATT_PAD + j];
                pr[i][0] = t.x; pr[i][1] = t.y; pr[i][2] = t.z; pr[i][3] = t.w;
            }
#pragma unroll
            for (int jj = 0; jj < 4; jj++) {
                float4 vv = *(const float4*)&Vs[(j + jj) * ATT_PAD + col0];
#pragma unroll
                for (int i = 0; i < 4; i++) {
                    acc[i][0] += pr[i][jj] * vv.x;
                    acc[i][1] += pr[i][jj] * vv.y;
                    acc[i][2] += pr[i][jj] * vv.z;
                    acc[i][3] += pr[i][jj] * vv.w;
                }
            }
        }
    }
    __syncthreads();

#pragma unroll
    for (int i = 0; i < 4; i++) {
        int gr = m0 + row0 + i;
        float inv = 1.0f / l_s[row0 + i];
        float4 o = make_float4(acc[i][0] * inv, acc[i][1] * inv, acc[i][2] * inv, acc[i][3] * inv);
        *(float4*)(ctx + (size_t)(b * L_ + gr) * (H_ * D_) + h * D_ + col0) = o;
    }
}

// ---------------- launch ----------------
extern "C" void kernel_launch(void* const* d_in, const int* in_sizes, int n_in,
                              void* d_out, int out_size) {
    (void)in_sizes; (void)n_in; (void)out_size;
    const float* X    = (const float*)d_in[0];
    // d_in[1] encoder_out: unused by reference
    const float* Wqkv = (const float*)d_in[2];
    const float* bqkv = (const float*)d_in[3];
    const float* Wo   = (const float*)d_in[4];
    const float* bo   = (const float*)d_in[5];
    // d_in[6..11]: cross-attention params, unused by reference
    const float* Ww   = (const float*)d_in[12];
    const float* Wv   = (const float*)d_in[13];
    const float* Wout = (const float*)d_in[14];
    float* out = (float*)d_out;

    float *h_p, *qkv_p, *ctx_p, *x_p, *g_p, *v_p;
    cudaGetSymbolAddress((void**)&h_p,   g_h);
    cudaGetSymbolAddress((void**)&qkv_p, g_qkv);
    cudaGetSymbolAddress((void**)&ctx_p, g_ctx);
    cudaGetSymbolAddress((void**)&x_p,   g_x);
    cudaGetSymbolAddress((void**)&g_p,   g_gate);
    cudaGetSymbolAddress((void**)&v_p,   g_val);

    cudaFuncSetAttribute(attn_kernel, cudaFuncAttributeMaxDynamicSharedMemorySize, ATT_SMEM);

    // 1. h = rmsnorm(X)
    rmsnorm_kernel<<<M_, 256>>>(X, h_p);
    // 2. qkv = h @ Wqkv + bqkv
    sgemm_kernel<<<dim3(3 * H_ * D_ / 128, M_ / 128), 256>>>(
        M_, 3 * H_ * D_, E_, h_p, Wqkv, bqkv, nullptr, qkv_p);
    // 3. ctx = attention(Q,K,V) with alibi+causal
    attn_kernel<<<dim3(L_ / 64, H_, B_), 256, ATT_SMEM>>>(qkv_p, ctx_p);
    // 4. x = X + ctx @ Wo + bo
    sgemm_kernel<<<dim3(E_ / 128, M_ / 128), 256>>>(
        M_, E_, H_ * D_, ctx_p, Wo, bo, X, x_p);
    // 5+6. x = x + rmsnorm(x); h = rmsnorm(x)
    addnorm_kernel<<<M_, 256>>>(x_p, h_p);
    // 7. gate = h @ Ww ; val = h @ Wv
    sgemm_kernel<<<dim3(DFF_ / 128, M_ / 128), 256>>>(
        M_, DFF_, E_, h_p, Ww, nullptr, nullptr, g_p);
    sgemm_kernel<<<dim3(DFF_ / 128, M_ / 128), 256>>>(
        M_, DFF_, E_, h_p, Wv, nullptr, nullptr, v_p);
    // 8. gate = gelu(gate) * val
    geglu_kernel<<<(M_ * DFF_) / 256, 256>>>(g_p, v_p);
    // 9. out = x + gate @ Wout
    sgemm_kernel<<<dim3(E_ / 128, M_ / 128), 256>>>(
        M_, E_, DFF_, g_p, Wout, nullptr, x_p, out);
}

// round 2
// speedup vs baseline: 2.0676x; 2.0676x over previous
#include <cuda_runtime.h>
#include <math_constants.h>
#include <cstdint>

#define B_   2
#define L_   2048
#define E_   1024
#define H_   16
#define D_   64
#define DFF_ 4096
#define M_   (B_ * L_)   // 4096 tokens

// ---------------- scratch (device globals: allocation-guard safe) ----------------
__device__ float g_h[M_ * E_];
__device__ float g_qkv[(size_t)M_ * 3 * H_ * D_];
__device__ float g_ctx[M_ * H_ * D_];
__device__ float g_x[M_ * E_];
__device__ float g_gate[(size_t)M_ * DFF_];
__device__ float g_val[(size_t)M_ * DFF_];

// ---------------- rmsnorm ----------------
__global__ __launch_bounds__(256) void rmsnorm_kernel(const float* __restrict__ x,
                                                      float* __restrict__ y) {
    int row = blockIdx.x;
    float4 a = ((const float4*)(x + (size_t)row * E_))[threadIdx.x];
    float ss = a.x * a.x + a.y * a.y + a.z * a.z + a.w * a.w;
    __shared__ float red[8];
    __shared__ float sinv;
#pragma unroll
    for (int o = 16; o > 0; o >>= 1) ss += __shfl_xor_sync(0xffffffffu, ss, o);
    if ((threadIdx.x & 31) == 0) red[threadIdx.x >> 5] = ss;
    __syncthreads();
    if (threadIdx.x == 0) {
        float t = 0.f;
#pragma unroll
        for (int i = 0; i < 8; i++) t += red[i];
        sinv = rsqrtf(t * (1.0f / E_));
    }
    __syncthreads();
    float c = sinv;
    float4 o = make_float4(a.x * c, a.y * c, a.z * c, a.w * c);
    ((float4*)(y + (size_t)row * E_))[threadIdx.x] = o;
}

// ---------------- fused: x = x + rmsnorm(x);  h = rmsnorm(x) ----------------
__global__ __launch_bounds__(256) void addnorm_kernel(float* __restrict__ x,
                                                      float* __restrict__ h) {
    int row = blockIdx.x;
    float4 a = ((const float4*)(x + (size_t)row * E_))[threadIdx.x];
    __shared__ float red[8];
    __shared__ float sval;
    float ss = a.x * a.x + a.y * a.y + a.z * a.z + a.w * a.w;
#pragma unroll
    for (int o = 16; o > 0; o >>= 1) ss += __shfl_xor_sync(0xffffffffu, ss, o);
    if ((threadIdx.x & 31) == 0) red[threadIdx.x >> 5] = ss;
    __syncthreads();
    if (threadIdx.x == 0) {
        float t = 0.f;
#pragma unroll
        for (int i = 0; i < 8; i++) t += red[i];
        sval = 1.0f + rsqrtf(t * (1.0f / E_));
    }
    __syncthreads();
    float c = sval;
    a.x *= c; a.y *= c; a.z *= c; a.w *= c;
    float ss2 = a.x * a.x + a.y * a.y + a.z * a.z + a.w * a.w;
#pragma unroll
    for (int o = 16; o > 0; o >>= 1) ss2 += __shfl_xor_sync(0xffffffffu, ss2, o);
    if ((threadIdx.x & 31) == 0) red[threadIdx.x >> 5] = ss2;
    __syncthreads();
    if (threadIdx.x == 0) {
        float t = 0.f;
#pragma unroll
        for (int i = 0; i < 8; i++) t += red[i];
        sval = rsqrtf(t * (1.0f / E_));
    }
    __syncthreads();
    float inv2 = sval;
    ((float4*)(x + (size_t)row * E_))[threadIdx.x] = a;
    float4 o = make_float4(a.x * inv2, a.y * inv2, a.z * inv2, a.w * inv2);
    ((float4*)(h + (size_t)row * E_))[threadIdx.x] = o;
}

// ---------------- geglu ----------------
__global__ __launch_bounds__(256) void geglu_kernel(float* __restrict__ g,
                                                    const float* __restrict__ v) {
    int i = blockIdx.x * 256 + threadIdx.x;
    float x = g[i];
    float gel = 0.5f * x * (1.0f + erff(x * 0.70710678118654752f));
    g[i] = gel * v[i];
}

// ================= tf32 tensor-core GEMM =================
// C(MxN) = A(MxK) @ B(KxN) [+bias] [+res], all fp32 storage, tf32 mma.
// 128x128x32 CTA tile, 256 threads, 8 warps in 2x4 grid, 64x32 warp tile,
// m16n8k8 mma, cp.async double-buffered smem.
#define BM 128
#define BN 128
#define BK 32
#define APAD 4                        // A row stride 36 -> frag banks 4r+c (conflict-free)
#define BPAD 8                        // B row stride 136 -> frag banks 8c+q (conflict-free)
#define ASTRIDE (BK + APAD)           // 36
#define BSTRIDE (BN + BPAD)           // 136
#define TG_SMEM ((2 * BM * ASTRIDE + 2 * BK * BSTRIDE) * 4)  // 71680 B

__device__ __forceinline__ uint32_t f2tf(float f) {
    uint32_t u;
    asm("cvt.rna.tf32.f32 %0, %1;" : "=r"(u) : "f"(f));
    return u;
}

__device__ __forceinline__ void mma_tf32(float* d, const uint32_t* a, const uint32_t* b) {
    asm volatile(
        "mma.sync.aligned.m16n8k8.row.col.f32.tf32.tf32.f32 "
        "{%0,%1,%2,%3}, {%4,%5,%6,%7}, {%8,%9}, {%0,%1,%2,%3};\n"
        : "+f"(d[0]), "+f"(d[1]), "+f"(d[2]), "+f"(d[3])
        : "r"(a[0]), "r"(a[1]), "r"(a[2]), "r"(a[3]), "r"(b[0]), "r"(b[1]));
}

__global__ __launch_bounds__(256, 2) void tgemm_kernel(
    int M, int N, int K,
    const float* __restrict__ A, const float* __restrict__ B,
    const float* __restrict__ bias, const float* __restrict__ res,
    float* __restrict__ C) {
    extern __shared__ float sm[];
    float* As = sm;                               // [2][BM][ASTRIDE]
    float* Bs = sm + 2 * BM * ASTRIDE;            // [2][BK][BSTRIDE]

    const int tid  = threadIdx.x;
    const int bm   = blockIdx.y * BM;
    const int bn   = blockIdx.x * BN;
    const int warp = tid >> 5, lane = tid & 31;
    const int wm   = (warp >> 2) * 64;            // 0 or 64
    const int wn   = (warp & 3) * 32;             // 0,32,64,96
    const int fr   = lane >> 2;                   // 0..7
    const int fc   = lane & 3;                    // 0..3

    // copy indices
    const int ar = tid >> 3;                      // 0..31 (A row within pass)
    const int ac = (tid & 7) * 4;                 // A k-offset
    const int br = tid >> 5;                      // 0..7  (B row within pass)
    const int bc = (tid & 31) * 4;                // B n-offset

    float acc[4][4][4];
#pragma unroll
    for (int i = 0; i < 4; i++)
#pragma unroll
        for (int j = 0; j < 4; j++)
#pragma unroll
            for (int k = 0; k < 4; k++) acc[i][j][k] = 0.f;

    auto issue_loads = [&](int s, int kt) {
        float* Ad = As + s * BM * ASTRIDE;
        float* Bd = Bs + s * BK * BSTRIDE;
#pragma unroll
        for (int p = 0; p < 4; p++) {
            int row = p * 32 + ar;
            uint32_t dst = (uint32_t)__cvta_generic_to_shared(Ad + row * ASTRIDE + ac);
            const float* src = A + (size_t)(bm + row) * K + kt + ac;
            asm volatile("cp.async.cg.shared.global [%0], [%1], 16;\n" :: "r"(dst), "l"(src));
        }
#pragma unroll
        for (int p = 0; p < 4; p++) {
            int row = p * 8 + br;
            uint32_t dst = (uint32_t)__cvta_generic_to_shared(Bd + row * BSTRIDE + bc);
            const float* src = B + (size_t)(kt + row) * N + bn + bc;
            asm volatile("cp.async.cg.shared.global [%0], [%1], 16;\n" :: "r"(dst), "l"(src));
        }
        asm volatile("cp.async.commit_group;\n");
    };

    auto compute_tile = [&](int s) {
        const float* Ab = As + s * BM * ASTRIDE;
        const float* Bb = Bs + s * BK * BSTRIDE;
#pragma unroll
        for (int ks = 0; ks < 4; ks++) {
            const int k0 = ks * 8;
            uint32_t af[4][4], bf[4][2];
#pragma unroll
            for (int mi = 0; mi < 4; mi++) {
                int m = wm + mi * 16 + fr;
                af[mi][0] = f2tf(Ab[m * ASTRIDE + k0 + fc]);
                af[mi][1] = f2tf(Ab[(m + 8) * ASTRIDE + k0 + fc]);
                af[mi][2] = f2tf(Ab[m * ASTRIDE + k0 + fc + 4]);
                af[mi][3] = f2tf(Ab[(m + 8) * ASTRIDE + k0 + fc + 4]);
            }
#pragma unroll
            for (int ni = 0; ni < 4; ni++) {
                int n = wn + ni * 8 + fr;
                bf[ni][0] = f2tf(Bb[(k0 + fc) * BSTRIDE + n]);
                bf[ni][1] = f2tf(Bb[(k0 + fc + 4) * BSTRIDE + n]);
            }
#pragma unroll
            for (int mi = 0; mi < 4; mi++)
#pragma unroll
                for (int ni = 0; ni < 4; ni++) mma_tf32(acc[mi][ni], af[mi], bf[ni]);
        }
    };

    const int kiters = K / BK;
    issue_loads(0, 0);
    asm volatile("cp.async.wait_group 0;\n");
    __syncthreads();

#pragma unroll 1
    for (int it = 0; it < kiters; ++it) {
        int cur = it & 1;
        if (it + 1 < kiters) issue_loads(cur ^ 1, (it + 1) * BK);
        compute_tile(cur);
        asm volatile("cp.async.wait_group 0;\n");
        __syncthreads();
    }

    // epilogue
#pragma unroll
    for (int mi = 0; mi < 4; mi++) {
#pragma unroll
        for (int ni = 0; ni < 4; ni++) {
            int gr = bm + wm + mi * 16 + fr;
            int gc = bn + wn + ni * 8 + fc * 2;
            float2 o0 = make_float2(acc[mi][ni][0], acc[mi][ni][1]);
            float2 o1 = make_float2(acc[mi][ni][2], acc[mi][ni][3]);
            if (bias) {
                float2 bv = *(const float2*)(bias + gc);
                o0.x += bv.x; o0.y += bv.y;
                o1.x += bv.x; o1.y += bv.y;
            }
            if (res) {
                float2 r0 = *(const float2*)(res + (size_t)gr * N + gc);
                float2 r1 = *(const float2*)(res + (size_t)(gr + 8) * N + gc);
                o0.x += r0.x; o0.y += r0.y;
                o1.x += r1.x; o1.y += r1.y;
            }
            *(float2*)(C + (size_t)gr * N + gc) = o0;
            *(float2*)(C + (size_t)(gr + 8) * N + gc) = o1;
        }
    }
}

// ---------------- flash attention with ALiBi + causal (unchanged) ----------------
#define ATT_PAD 68
#define ATT_SMEM ((4 * 64 * ATT_PAD + 3 * 64) * 4)

__global__ __launch_bounds__(256) void attn_kernel(const float* __restrict__ qkv,
                                                   float* __restrict__ ctx) {
    extern __shared__ float smr[];
    float* Qs  = smr;
    float* Ks  = Qs + 64 * ATT_PAD;
    float* Vs  = Ks + 64 * ATT_PAD;
    float* Ps  = Vs + 64 * ATT_PAD;
    float* m_s = Ps + 64 * ATT_PAD;
    float* l_s = m_s + 64;
    float* a_s = l_s + 64;

    const int qt = blockIdx.x, h = blockIdx.y, b = blockIdx.z;
    const int m0 = qt * 64;
    const int tid = threadIdx.x;
    const float slope = exp2f(-(1.0f + 7.0f * (float)h / 15.0f));

    for (int i = tid; i < 64 * 16; i += 256) {
        int r = i >> 4, c = (i & 15) << 2;
        float4 v = *(const float4*)(qkv + ((((size_t)(b * L_ + m0 + r) * H_ + h) * 3 + 0) * D_ + c));
        Qs[r * ATT_PAD + c + 0] = v.x * 0.125f;
        Qs[r * ATT_PAD + c + 1] = v.y * 0.125f;
        Qs[r * ATT_PAD + c + 2] = v.z * 0.125f;
        Qs[r * ATT_PAD + c + 3] = v.w * 0.125f;
    }
    if (tid < 64) { m_s[tid] = -CUDART_INF_F; l_s[tid] = 0.f; }

    float acc[4][4];
#pragma unroll
    for (int i = 0; i < 4; i++)
#pragma unroll
        for (int j = 0; j < 4; j++) acc[i][j] = 0.f;

    const int tx = tid & 15, ty = tid >> 4;
    const int row0 = ty * 4, col0 = tx * 4;
    const int warp = tid >> 5, lane = tid & 31;

    for (int kt = 0; kt <= qt; kt++) {
        const int n0 = kt * 64;
        __syncthreads();
        for (int i = tid; i < 64 * 16; i += 256) {
            int r = i >> 4, c = (i & 15) << 2;
            size_t base = ((size_t)(b * L_ + n0 + r) * H_ + h) * 3;
            float4 kv = *(const float4*)(qkv + (base + 1) * D_ + c);
            float4 vv = *(const float4*)(qkv + (base + 2) * D_ + c);
            Ks[r * ATT_PAD + c + 0] = kv.x; Ks[r * ATT_PAD + c + 1] = kv.y;
            Ks[r * ATT_PAD + c + 2] = kv.z; Ks[r * ATT_PAD + c + 3] = kv.w;
            Vs[r * ATT_PAD + c + 0] = vv.x; Vs[r * ATT_PAD + c + 1] = vv.y;
            Vs[r * ATT_PAD + c + 2] = vv.z; Vs[r * ATT_PAD + c + 3] = vv.w;
        }
        __syncthreads();

        float s[4][4];
#pragma unroll
        for (int i = 0; i < 4; i++)
#pragma unroll
            for (int j = 0; j < 4; j++) s[i][j] = 0.f;
#pragma unroll
        for (int d = 0; d < 64; d += 4) {
            float qa[4][4], kb[4][4];
#pragma unroll
            for (int i = 0; i < 4; i++) {
                float4 t = *(const float4*)&Qs[(row0 + i) * ATT_PAD + d];
                qa[i][0] = t.x; qa[i][1] = t.y; qa[i][2] = t.z; qa[i][3] = t.w;
            }
#pragma unroll
            for (int j = 0; j < 4; j++) {
                float4 t = *(const float4*)&Ks[(col0 + j) * ATT_PAD + d];
                kb[j][0] = t.x; kb[j][1] = t.y; kb[j][2] = t.z; kb[j][3] = t.w;
            }
#pragma unroll
            for (int dd = 0; dd < 4; dd++)
#pragma unroll
                for (int i = 0; i < 4; i++)
#pragma unroll
                    for (int j = 0; j < 4; j++) s[i][j] += qa[i][dd] * kb[j][dd];
        }
#pragma unroll
        for (int i = 0; i < 4; i++)
#pragma unroll
            for (int j = 0; j < 4; j++) {
                int gi = m0 + row0 + i, gj = n0 + col0 + j;
                float v = s[i][j] + slope * (float)(gj - gi);
                if (gj > gi) v = -CUDART_INF_F;
                Ps[(row0 + i) * ATT_PAD + col0 + j] = v;
            }
        __syncthreads();

#pragma unroll
        for (int rr = 0; rr < 8; rr++) {
            int r = warp * 8 + rr;
            float v0 = Ps[r * ATT_PAD + lane];
            float v1 = Ps[r * ATT_PAD + 32 + lane];
            float mx = fmaxf(v0, v1);
#pragma unroll
            for (int o = 16; o > 0; o >>= 1) mx = fmaxf(mx, __shfl_xor_sync(0xffffffffu, mx, o));
            float mo = m_s[r];
            float mn = fmaxf(mo, mx);
            float p0 = __expf(v0 - mn);
            float p1 = __expf(v1 - mn);
            float sum = p0 + p1;
#pragma unroll
            for (int o = 16; o > 0; o >>= 1) sum += __shfl_xor_sync(0xffffffffu, sum, o);
            Ps[r * ATT_PAD + lane] = p0;
            Ps[r * ATT_PAD + 32 + lane] = p1;
            if (lane == 0) {
                float al = __expf(mo - mn);
                l_s[r] = l_s[r] * al + sum;
                m_s[r] = mn;
                a_s[r] = al;
            }
        }
        __syncthreads();

        float al[4];
#pragma unroll
        for (int i = 0; i < 4; i++) al[i] = a_s[row0 + i];
#pragma unroll
        for (int i = 0; i < 4; i++)
#pragma unroll
            for (int j = 0; j < 4; j++) acc[i][j] *= al[i];
#pragma unroll
        for (int j = 0; j < 64; j += 4) {
            float pr[4][4];
#pragma unroll
            for (int i = 0; i < 4; i++) {
                float4 t = *(const float4*)&Ps[(row0 + i) * ATT_PAD + j];
                pr[i][0] = t.x; pr[i][1] = t.y; pr[i][2] = t.z; pr[i][3] = t.w;
            }
#pragma unroll
            for (int jj = 0; jj < 4; jj++) {
                float4 vv = *(const float4*)&Vs[(j + jj) * ATT_PAD + col0];
#pragma unroll
                for (int i = 0; i < 4; i++) {
                    acc[i][0] += pr[i][jj] * vv.x;
                    acc[i][1] += pr[i][jj] * vv.y;
                    acc[i][2] += pr[i][jj] * vv.z;
                    acc[i][3] += pr[i][jj] * vv.w;
                }
            }
        }
    }
    __syncthreads();

#pragma unroll
    for (int i = 0; i < 4; i++) {
        int gr = m0 + row0 + i;
        float inv = 1.0f / l_s[row0 + i];
        float4 o = make_float4(acc[i][0] * inv, acc[i][1] * inv, acc[i][2] * inv, acc[i][3] * inv);
        *(float4*)(ctx + (size_t)(b * L_ + gr) * (H_ * D_) + h * D_ + col0) = o;
    }
}

// ---------------- launch ----------------
extern "C" void kernel_launch(void* const* d_in, const int* in_sizes, int n_in,
                              void* d_out, int out_size) {
    (void)in_sizes; (void)n_in; (void)out_size;
    const float* X    = (const float*)d_in[0];
    const float* Wqkv = (const float*)d_in[2];
    const float* bqkv = (const float*)d_in[3];
    const float* Wo   = (const float*)d_in[4];
    const float* bo   = (const float*)d_in[5];
    const float* Ww   = (const float*)d_in[12];
    const float* Wv   = (const float*)d_in[13];
    const float* Wout = (const float*)d_in[14];
    float* out = (float*)d_out;

    float *h_p, *qkv_p, *ctx_p, *x_p, *g_p, *v_p;
    cudaGetSymbolAddress((void**)&h_p,   g_h);
    cudaGetSymbolAddress((void**)&qkv_p, g_qkv);
    cudaGetSymbolAddress((void**)&ctx_p, g_ctx);
    cudaGetSymbolAddress((void**)&x_p,   g_x);
    cudaGetSymbolAddress((void**)&g_p,   g_gate);
    cudaGetSymbolAddress((void**)&v_p,   g_val);

    cudaFuncSetAttribute(attn_kernel, cudaFuncAttributeMaxDynamicSharedMemorySize, ATT_SMEM);
    cudaFuncSetAttribute(tgemm_kernel, cudaFuncAttributeMaxDynamicSharedMemorySize, TG_SMEM);

    // 1. h = rmsnorm(X)
    rmsnorm_kernel<<<M_, 256>>>(X, h_p);
    // 2. qkv = h @ Wqkv + bqkv
    tgemm_kernel<<<dim3(3 * H_ * D_ / BN, M_ / BM), 256, TG_SMEM>>>(
        M_, 3 * H_ * D_, E_, h_p, Wqkv, bqkv, nullptr, qkv_p);
    // 3. attention
    attn_kernel<<<dim3(L_ / 64, H_, B_), 256, ATT_SMEM>>>(qkv_p, ctx_p);
    // 4. x = X + ctx @ Wo + bo
    tgemm_kernel<<<dim3(E_ / BN, M_ / BM), 256, TG_SMEM>>>(
        M_, E_, H_ * D_, ctx_p, Wo, bo, X, x_p);
    // 5+6. x = x + rmsnorm(x); h = rmsnorm(x)
    addnorm_kernel<<<M_, 256>>>(x_p, h_p);
    // 7. gate = h @ Ww ; val = h @ Wv
    tgemm_kernel<<<dim3(DFF_ / BN, M_ / BM), 256, TG_SMEM>>>(
        M_, DFF_, E_, h_p, Ww, nullptr, nullptr, g_p);
    tgemm_kernel<<<dim3(DFF_ / BN, M_ / BM), 256, TG_SMEM>>>(
        M_, DFF_, E_, h_p, Wv, nullptr, nullptr, v_p);
    // 8. gate = gelu(gate) * val
    geglu_kernel<<<(M_ * DFF_) / 256, 256>>>(g_p, v_p);
    // 9. out = x + gate @ Wout
    tgemm_kernel<<<dim3(E_ / BN, M_ / BM), 256, TG_SMEM>>>(
        M_, E_, DFF_, g_p, Wout, nullptr, x_p, out);
}

// round 3
// speedup vs baseline: 3.2533x; 1.5734x over previous
#include <cuda_runtime.h>
#include <math_constants.h>
#include <cstdint>

#define B_   2
#define L_   2048
#define E_   1024
#define H_   16
#define D_   64
#define DFF_ 4096
#define M_   (B_ * L_)   // 4096 tokens

// ---------------- scratch (device globals: allocation-guard safe) ----------------
__device__ float g_h[M_ * E_];
__device__ float g_qkv[(size_t)M_ * 3 * H_ * D_];
__device__ float g_ctx[M_ * H_ * D_];
__device__ float g_x[M_ * E_];
__device__ float g_gate[(size_t)M_ * DFF_];
__device__ float g_val[(size_t)M_ * DFF_];

// ---------------- rmsnorm ----------------
__global__ __launch_bounds__(256) void rmsnorm_kernel(const float* __restrict__ x,
                                                      float* __restrict__ y) {
    int row = blockIdx.x;
    float4 a = ((const float4*)(x + (size_t)row * E_))[threadIdx.x];
    float ss = a.x * a.x + a.y * a.y + a.z * a.z + a.w * a.w;
    __shared__ float red[8];
    __shared__ float sinv;
#pragma unroll
    for (int o = 16; o > 0; o >>= 1) ss += __shfl_xor_sync(0xffffffffu, ss, o);
    if ((threadIdx.x & 31) == 0) red[threadIdx.x >> 5] = ss;
    __syncthreads();
    if (threadIdx.x == 0) {
        float t = 0.f;
#pragma unroll
        for (int i = 0; i < 8; i++) t += red[i];
        sinv = rsqrtf(t * (1.0f / E_));
    }
    __syncthreads();
    float c = sinv;
    float4 o = make_float4(a.x * c, a.y * c, a.z * c, a.w * c);
    ((float4*)(y + (size_t)row * E_))[threadIdx.x] = o;
}

// ---------------- fused: x = x + rmsnorm(x);  h = rmsnorm(x) ----------------
__global__ __launch_bounds__(256) void addnorm_kernel(float* __restrict__ x,
                                                      float* __restrict__ h) {
    int row = blockIdx.x;
    float4 a = ((const float4*)(x + (size_t)row * E_))[threadIdx.x];
    __shared__ float red[8];
    __shared__ float sval;
    float ss = a.x * a.x + a.y * a.y + a.z * a.z + a.w * a.w;
#pragma unroll
    for (int o = 16; o > 0; o >>= 1) ss += __shfl_xor_sync(0xffffffffu, ss, o);
    if ((threadIdx.x & 31) == 0) red[threadIdx.x >> 5] = ss;
    __syncthreads();
    if (threadIdx.x == 0) {
        float t = 0.f;
#pragma unroll
        for (int i = 0; i < 8; i++) t += red[i];
        sval = 1.0f + rsqrtf(t * (1.0f / E_));
    }
    __syncthreads();
    float c = sval;
    a.x *= c; a.y *= c; a.z *= c; a.w *= c;
    float ss2 = a.x * a.x + a.y * a.y + a.z * a.z + a.w * a.w;
#pragma unroll
    for (int o = 16; o > 0; o >>= 1) ss2 += __shfl_xor_sync(0xffffffffu, ss2, o);
    if ((threadIdx.x & 31) == 0) red[threadIdx.x >> 5] = ss2;
    __syncthreads();
    if (threadIdx.x == 0) {
        float t = 0.f;
#pragma unroll
        for (int i = 0; i < 8; i++) t += red[i];
        sval = rsqrtf(t * (1.0f / E_));
    }
    __syncthreads();
    float inv2 = sval;
    ((float4*)(x + (size_t)row * E_))[threadIdx.x] = a;
    float4 o = make_float4(a.x * inv2, a.y * inv2, a.z * inv2, a.w * inv2);
    ((float4*)(h + (size_t)row * E_))[threadIdx.x] = o;
}

// ---------------- geglu ----------------
__global__ __launch_bounds__(256) void geglu_kernel(float* __restrict__ g,
                                                    const float* __restrict__ v) {
    int i = blockIdx.x * 256 + threadIdx.x;
    float x = g[i];
    float gel = 0.5f * x * (1.0f + erff(x * 0.70710678118654752f));
    g[i] = gel * v[i];
}

// ================= tf32 mma helpers =================
__device__ __forceinline__ uint32_t f2tf(float f) {
    uint32_t u;
    asm("cvt.rna.tf32.f32 %0, %1;" : "=r"(u) : "f"(f));
    return u;
}

__device__ __forceinline__ void mma_tf32(float* d, const uint32_t* a, const uint32_t* b) {
    asm volatile(
        "mma.sync.aligned.m16n8k8.row.col.f32.tf32.tf32.f32 "
        "{%0,%1,%2,%3}, {%4,%5,%6,%7}, {%8,%9}, {%0,%1,%2,%3};\n"
        : "+f"(d[0]), "+f"(d[1]), "+f"(d[2]), "+f"(d[3])
        : "r"(a[0]), "r"(a[1]), "r"(a[2]), "r"(a[3]), "r"(b[0]), "r"(b[1]));
}

// ================= tf32 tensor-core GEMM (unchanged from R2) =================
#define BM 128
#define BN 128
#define BK 32
#define APAD 4
#define BPAD 8
#define ASTRIDE (BK + APAD)           // 36
#define BSTRIDE (BN + BPAD)           // 136
#define TG_SMEM ((2 * BM * ASTRIDE + 2 * BK * BSTRIDE) * 4)  // 71680 B

__global__ __launch_bounds__(256, 2) void tgemm_kernel(
    int M, int N, int K,
    const float* __restrict__ A, const float* __restrict__ B,
    const float* __restrict__ bias, const float* __restrict__ res,
    float* __restrict__ C) {
    extern __shared__ float sm[];
    float* As = sm;
    float* Bs = sm + 2 * BM * ASTRIDE;

    const int tid  = threadIdx.x;
    const int bm   = blockIdx.y * BM;
    const int bn   = blockIdx.x * BN;
    const int warp = tid >> 5, lane = tid & 31;
    const int wm   = (warp >> 2) * 64;
    const int wn   = (warp & 3) * 32;
    const int fr   = lane >> 2;
    const int fc   = lane & 3;

    const int ar = tid >> 3;
    const int ac = (tid & 7) * 4;
    const int br = tid >> 5;
    const int bc = (tid & 31) * 4;

    float acc[4][4][4];
#pragma unroll
    for (int i = 0; i < 4; i++)
#pragma unroll
        for (int j = 0; j < 4; j++)
#pragma unroll
            for (int k = 0; k < 4; k++) acc[i][j][k] = 0.f;

    auto issue_loads = [&](int s, int kt) {
        float* Ad = As + s * BM * ASTRIDE;
        float* Bd = Bs + s * BK * BSTRIDE;
#pragma unroll
        for (int p = 0; p < 4; p++) {
            int row = p * 32 + ar;
            uint32_t dst = (uint32_t)__cvta_generic_to_shared(Ad + row * ASTRIDE + ac);
            const float* src = A + (size_t)(bm + row) * K + kt + ac;
            asm volatile("cp.async.cg.shared.global [%0], [%1], 16;\n" :: "r"(dst), "l"(src));
        }
#pragma unroll
        for (int p = 0; p < 4; p++) {
            int row = p * 8 + br;
            uint32_t dst = (uint32_t)__cvta_generic_to_shared(Bd + row * BSTRIDE + bc);
            const float* src = B + (size_t)(kt + row) * N + bn + bc;
            asm volatile("cp.async.cg.shared.global [%0], [%1], 16;\n" :: "r"(dst), "l"(src));
        }
        asm volatile("cp.async.commit_group;\n");
    };

    auto compute_tile = [&](int s) {
        const float* Ab = As + s * BM * ASTRIDE;
        const float* Bb = Bs + s * BK * BSTRIDE;
#pragma unroll
        for (int ks = 0; ks < 4; ks++) {
            const int k0 = ks * 8;
            uint32_t af[4][4], bf[4][2];
#pragma unroll
            for (int mi = 0; mi < 4; mi++) {
                int m = wm + mi * 16 + fr;
                af[mi][0] = f2tf(Ab[m * ASTRIDE + k0 + fc]);
                af[mi][1] = f2tf(Ab[(m + 8) * ASTRIDE + k0 + fc]);
                af[mi][2] = f2tf(Ab[m * ASTRIDE + k0 + fc + 4]);
                af[mi][3] = f2tf(Ab[(m + 8) * ASTRIDE + k0 + fc + 4]);
            }
#pragma unroll
            for (int ni = 0; ni < 4; ni++) {
                int n = wn + ni * 8 + fr;
                bf[ni][0] = f2tf(Bb[(k0 + fc) * BSTRIDE + n]);
                bf[ni][1] = f2tf(Bb[(k0 + fc + 4) * BSTRIDE + n]);
            }
#pragma unroll
            for (int mi = 0; mi < 4; mi++)
#pragma unroll
                for (int ni = 0; ni < 4; ni++) mma_tf32(acc[mi][ni], af[mi], bf[ni]);
        }
    };

    const int kiters = K / BK;
    issue_loads(0, 0);
    asm volatile("cp.async.wait_group 0;\n");
    __syncthreads();

#pragma unroll 1
    for (int it = 0; it < kiters; ++it) {
        int cur = it & 1;
        if (it + 1 < kiters) issue_loads(cur ^ 1, (it + 1) * BK);
        compute_tile(cur);
        asm volatile("cp.async.wait_group 0;\n");
        __syncthreads();
    }

#pragma unroll
    for (int mi = 0; mi < 4; mi++) {
#pragma unroll
        for (int ni = 0; ni < 4; ni++) {
            int gr = bm + wm + mi * 16 + fr;
            int gc = bn + wn + ni * 8 + fc * 2;
            float2 o0 = make_float2(acc[mi][ni][0], acc[mi][ni][1]);
            float2 o1 = make_float2(acc[mi][ni][2], acc[mi][ni][3]);
            if (bias) {
                float2 bv = *(const float2*)(bias + gc);
                o0.x += bv.x; o0.y += bv.y;
                o1.x += bv.x; o1.y += bv.y;
            }
            if (res) {
                float2 r0 = *(const float2*)(res + (size_t)gr * N + gc);
                float2 r1 = *(const float2*)(res + (size_t)(gr + 8) * N + gc);
                o0.x += r0.x; o0.y += r0.y;
                o1.x += r1.x; o1.y += r1.y;
            }
            *(float2*)(C + (size_t)gr * N + gc) = o0;
            *(float2*)(C + (size_t)(gr + 8) * N + gc) = o1;
        }
    }
}

// ================= tf32 tensor-core flash attention =================
// 64x64 Q-tile per CTA, 4 warps, each warp owns 16 query rows.
// Q: register A-fragments (converted once). K stored transposed [d][key] stride 72.
// V stored [key][d] stride 72. P round-trips via smem stride 68 (warp-private rows).
#define PQ_STRIDE 68   // == 4 mod 32 -> conflict-free A-fragment reads
#define KV_STRIDE 72   // == 8 mod 32 -> conflict-free B-fragment reads
#define ATT_SMEM ((64 * PQ_STRIDE * 2 + 64 * KV_STRIDE * 2) * 4)  // 71680 B

__global__ __launch_bounds__(128) void attn_kernel(const float* __restrict__ qkv,
                                                   float* __restrict__ ctx) {
    extern __shared__ float smr[];
    float* Qs = smr;                         // [64][68]
    float* Ps = Qs + 64 * PQ_STRIDE;         // [64][68]
    float* Ks = Ps + 64 * PQ_STRIDE;         // [64(d)][72(key)]  (transposed)
    float* Vs = Ks + 64 * KV_STRIDE;         // [64(key)][72(d)]

    const int qt = blockIdx.x, h = blockIdx.y, b = blockIdx.z;
    const int m0 = qt * 64;
    const int tid  = threadIdx.x;
    const int warp = tid >> 5, lane = tid & 31;
    const int fr = lane >> 2, fc = lane & 3;
    const int w16 = warp * 16;
    const float slope = exp2f(-(1.0f + 7.0f * (float)h / 15.0f));

    // ---- load Q tile (pre-scaled by 1/8) ----
    for (int i = tid; i < 64 * 16; i += 128) {
        int r = i >> 4, c = (i & 15) << 2;
        float4 v = *(const float4*)(qkv + ((((size_t)(b * L_ + m0 + r) * H_ + h) * 3 + 0) * D_ + c));
        Qs[r * PQ_STRIDE + c + 0] = v.x * 0.125f;
        Qs[r * PQ_STRIDE + c + 1] = v.y * 0.125f;
        Qs[r * PQ_STRIDE + c + 2] = v.z * 0.125f;
        Qs[r * PQ_STRIDE + c + 3] = v.w * 0.125f;
    }
    __syncthreads();

    // ---- Q A-fragments, register resident ----
    uint32_t qf[8][4];
#pragma unroll
    for (int ks = 0; ks < 8; ks++) {
        int k0 = ks * 8;
        qf[ks][0] = f2tf(Qs[(w16 + fr) * PQ_STRIDE + k0 + fc]);
        qf[ks][1] = f2tf(Qs[(w16 + fr + 8) * PQ_STRIDE + k0 + fc]);
        qf[ks][2] = f2tf(Qs[(w16 + fr) * PQ_STRIDE + k0 + fc + 4]);
        qf[ks][3] = f2tf(Qs[(w16 + fr + 8) * PQ_STRIDE + k0 + fc + 4]);
    }

    float oacc[8][4];
#pragma unroll
    for (int i = 0; i < 8; i++)
#pragma unroll
        for (int j = 0; j < 4; j++) oacc[i][j] = 0.f;
    float mrow0 = -CUDART_INF_F, mrow1 = -CUDART_INF_F;
    float lrow0 = 0.f, lrow1 = 0.f;

    const int gi0 = m0 + w16 + fr;
    const int gi1 = gi0 + 8;

    for (int kt = 0; kt <= qt; kt++) {
        const int n0 = kt * 64;
        __syncthreads();   // previous tile's mma reads of Ks/Vs done
        // ---- load K (transposed) + V ----
        for (int i = tid; i < 64 * 16; i += 128) {
            int r = i >> 4, c = (i & 15) << 2;
            size_t base = ((size_t)(b * L_ + n0 + r) * H_ + h) * 3;
            float4 kv = *(const float4*)(qkv + (base + 1) * D_ + c);
            float4 vv = *(const float4*)(qkv + (base + 2) * D_ + c);
            Ks[(c + 0) * KV_STRIDE + r] = kv.x;
            Ks[(c + 1) * KV_STRIDE + r] = kv.y;
            Ks[(c + 2) * KV_STRIDE + r] = kv.z;
            Ks[(c + 3) * KV_STRIDE + r] = kv.w;
            Vs[r * KV_STRIDE + c + 0] = vv.x;
            Vs[r * KV_STRIDE + c + 1] = vv.y;
            Vs[r * KV_STRIDE + c + 2] = vv.z;
            Vs[r * KV_STRIDE + c + 3] = vv.w;
        }
        __syncthreads();

        // ---- S = (Q/8) K^T via mma ----
        float sacc[8][4];
#pragma unroll
        for (int i = 0; i < 8; i++)
#pragma unroll
            for (int j = 0; j < 4; j++) sacc[i][j] = 0.f;
#pragma unroll
        for (int ks = 0; ks < 8; ks++) {
            int k0 = ks * 8;
            uint32_t bf[8][2];
#pragma unroll
            for (int ni = 0; ni < 8; ni++) {
                int n = ni * 8 + fr;
                bf[ni][0] = f2tf(Ks[(k0 + fc) * KV_STRIDE + n]);
                bf[ni][1] = f2tf(Ks[(k0 + fc + 4) * KV_STRIDE + n]);
            }
#pragma unroll
            for (int ni = 0; ni < 8; ni++) mma_tf32(sacc[ni], qf[ks], bf[ni]);
        }

        // ---- alibi + causal mask on fragments ----
#pragma unroll
        for (int ni = 0; ni < 8; ni++) {
            int gj = n0 + ni * 8 + 2 * fc;
            float a0 = slope * (float)(gj - gi0);
            float a1 = slope * (float)(gj + 1 - gi0);
            float a2 = slope * (float)(gj - gi1);
            float a3 = slope * (float)(gj + 1 - gi1);
            sacc[ni][0] = (gj     > gi0) ? -CUDART_INF_F : sacc[ni][0] + a0;
            sacc[ni][1] = (gj + 1 > gi0) ? -CUDART_INF_F : sacc[ni][1] + a1;
            sacc[ni][2] = (gj     > gi1) ? -CUDART_INF_F : sacc[ni][2] + a2;
            sacc[ni][3] = (gj + 1 > gi1) ? -CUDART_INF_F : sacc[ni][3] + a3;
        }

        // ---- online softmax on fragments (row spread over 4 lanes) ----
        float mx0 = -CUDART_INF_F, mx1 = -CUDART_INF_F;
#pragma unroll
        for (int ni = 0; ni < 8; ni++) {
            mx0 = fmaxf(mx0, fmaxf(sacc[ni][0], sacc[ni][1]));
            mx1 = fmaxf(mx1, fmaxf(sacc[ni][2], sacc[ni][3]));
        }
        mx0 = fmaxf(mx0, __shfl_xor_sync(0xffffffffu, mx0, 1));
        mx0 = fmaxf(mx0, __shfl_xor_sync(0xffffffffu, mx0, 2));
        mx1 = fmaxf(mx1, __shfl_xor_sync(0xffffffffu, mx1, 1));
        mx1 = fmaxf(mx1, __shfl_xor_sync(0xffffffffu, mx1, 2));
        float mn0 = fmaxf(mrow0, mx0);
        float mn1 = fmaxf(mrow1, mx1);
        float alpha0 = __expf(mrow0 - mn0);
        float alpha1 = __expf(mrow1 - mn1);
        float rs0 = 0.f, rs1 = 0.f;
#pragma unroll
        for (int ni = 0; ni < 8; ni++) {
            sacc[ni][0] = __expf(sacc[ni][0] - mn0);
            sacc[ni][1] = __expf(sacc[ni][1] - mn0);
            sacc[ni][2] = __expf(sacc[ni][2] - mn1);
            sacc[ni][3] = __expf(sacc[ni][3] - mn1);
            rs0 += sacc[ni][0] + sacc[ni][1];
            rs1 += sacc[ni][2] + sacc[ni][3];
        }
        rs0 += __shfl_xor_sync(0xffffffffu, rs0, 1);
        rs0 += __shfl_xor_sync(0xffffffffu, rs0, 2);
        rs1 += __shfl_xor_sync(0xffffffffu, rs1, 1);
        rs1 += __shfl_xor_sync(0xffffffffu, rs1, 2);
        lrow0 = lrow0 * alpha0 + rs0;
        lrow1 = lrow1 * alpha1 + rs1;
        mrow0 = mn0;
        mrow1 = mn1;
#pragma unroll
        for (int ni = 0; ni < 8; ni++) {
            oacc[ni][0] *= alpha0;
            oacc[ni][1] *= alpha0;
            oacc[ni][2] *= alpha1;
            oacc[ni][3] *= alpha1;
        }

        // ---- P fragments -> smem (warp-private rows) ----
#pragma unroll
        for (int ni = 0; ni < 8; ni++) {
            int c = ni * 8 + 2 * fc;
            *(float2*)&Ps[(w16 + fr) * PQ_STRIDE + c]     = make_float2(sacc[ni][0], sacc[ni][1]);
            *(float2*)&Ps[(w16 + fr + 8) * PQ_STRIDE + c] = make_float2(sacc[ni][2], sacc[ni][3]);
        }
        __syncwarp();

        // ---- O += P @ V via mma ----
#pragma unroll
        for (int ks = 0; ks < 8; ks++) {
            int k0 = ks * 8;
            uint32_t af[4];
            af[0] = f2tf(Ps[(w16 + fr) * PQ_STRIDE + k0 + fc]);
            af[1] = f2tf(Ps[(w16 + fr + 8) * PQ_STRIDE + k0 + fc]);
            af[2] = f2tf(Ps[(w16 + fr) * PQ_STRIDE + k0 + fc + 4]);
            af[3] = f2tf(Ps[(w16 + fr + 8) * PQ_STRIDE + k0 + fc + 4]);
#pragma unroll
            for (int ni = 0; ni < 8; ni++) {
                uint32_t bf[2];
                int n = ni * 8 + fr;
                bf[0] = f2tf(Vs[(k0 + fc) * KV_STRIDE + n]);
                bf[1] = f2tf(Vs[(k0 + fc + 4) * KV_STRIDE + n]);
                mma_tf32(oacc[ni], af, bf);
            }
        }
        __syncwarp();
    }

    // ---- epilogue ----
    float inv0 = 1.0f / lrow0;
    float inv1 = 1.0f / lrow1;
#pragma unroll
    for (int ni = 0; ni < 8; ni++) {
        int c = h * D_ + ni * 8 + 2 * fc;
        *(float2*)(ctx + (size_t)(b * L_ + gi0) * (H_ * D_) + c) =
            make_float2(oacc[ni][0] * inv0, oacc[ni][1] * inv0);
        *(float2*)(ctx + (size_t)(b * L_ + gi1) * (H_ * D_) + c) =
            make_float2(oacc[ni][2] * inv1, oacc[ni][3] * inv1);
    }
}

// ---------------- launch ----------------
extern "C" void kernel_launch(void* const* d_in, const int* in_sizes, int n_in,
                              void* d_out, int out_size) {
    (void)in_sizes; (void)n_in; (void)out_size;
    const float* X    = (const float*)d_in[0];
    const float* Wqkv = (const float*)d_in[2];
    const float* bqkv = (const float*)d_in[3];
    const float* Wo   = (const float*)d_in[4];
    const float* bo   = (const float*)d_in[5];
    const float* Ww   = (const float*)d_in[12];
    const float* Wv   = (const float*)d_in[13];
    const float* Wout = (const float*)d_in[14];
    float* out = (float*)d_out;

    float *h_p, *qkv_p, *ctx_p, *x_p, *g_p, *v_p;
    cudaGetSymbolAddress((void**)&h_p,   g_h);
    cudaGetSymbolAddress((void**)&qkv_p, g_qkv);
    cudaGetSymbolAddress((void**)&ctx_p, g_ctx);
    cudaGetSymbolAddress((void**)&x_p,   g_x);
    cudaGetSymbolAddress((void**)&g_p,   g_gate);
    cudaGetSymbolAddress((void**)&v_p,   g_val);

    cudaFuncSetAttribute(attn_kernel, cudaFuncAttributeMaxDynamicSharedMemorySize, ATT_SMEM);
    cudaFuncSetAttribute(tgemm_kernel, cudaFuncAttributeMaxDynamicSharedMemorySize, TG_SMEM);

    // 1. h = rmsnorm(X)
    rmsnorm_kernel<<<M_, 256>>>(X, h_p);
    // 2. qkv = h @ Wqkv + bqkv
    tgemm_kernel<<<dim3(3 * H_ * D_ / BN, M_ / BM), 256, TG_SMEM>>>(
        M_, 3 * H_ * D_, E_, h_p, Wqkv, bqkv, nullptr, qkv_p);
    // 3. attention (tf32 mma flash)
    attn_kernel<<<dim3(L_ / 64, H_, B_), 128, ATT_SMEM>>>(qkv_p, ctx_p);
    // 4. x = X + ctx @ Wo + bo
    tgemm_kernel<<<dim3(E_ / BN, M_ / BM), 256, TG_SMEM>>>(
        M_, E_, H_ * D_, ctx_p, Wo, bo, X, x_p);
    // 5+6. x = x + rmsnorm(x); h = rmsnorm(x)
    addnorm_kernel<<<M_, 256>>>(x_p, h_p);
    // 7. gate = h @ Ww ; val = h @ Wv
    tgemm_kernel<<<dim3(DFF_ / BN, M_ / BM), 256, TG_SMEM>>>(
        M_, DFF_, E_, h_p, Ww, nullptr, nullptr, g_p);
    tgemm_kernel<<<dim3(DFF_ / BN, M_ / BM), 256, TG_SMEM>>>(
        M_, DFF_, E_, h_p, Wv, nullptr, nullptr, v_p);
    // 8. gate = gelu(gate) * val
    geglu_kernel<<<(M_ * DFF_) / 256, 256>>>(g_p, v_p);
    // 9. out = x + gate @ Wout
    tgemm_kernel<<<dim3(E_ / BN, M_ / BM), 256, TG_SMEM>>>(
        M_, E_, DFF_, g_p, Wout, nullptr, x_p, out);
}

// round 4
// speedup vs baseline: 3.6343x; 1.1171x over previous
#include <cuda_runtime.h>
#include <math_constants.h>
#include <cstdint>

#define B_   2
#define L_   2048
#define E_   1024
#define H_   16
#define D_   64
#define DFF_ 4096
#define M_   (B_ * L_)   // 4096 tokens

// ---------------- scratch (device globals: allocation-guard safe) ----------------
__device__ float g_h[M_ * E_];
__device__ float g_qkv[(size_t)M_ * 3 * H_ * D_];
__device__ float g_ctx[M_ * H_ * D_];
__device__ float g_x[M_ * E_];
__device__ float g_gate[(size_t)M_ * DFF_];
__device__ float g_val[(size_t)M_ * DFF_];

// ---------------- rmsnorm ----------------
__global__ __launch_bounds__(256) void rmsnorm_kernel(const float* __restrict__ x,
                                                      float* __restrict__ y) {
    int row = blockIdx.x;
    float4 a = ((const float4*)(x + (size_t)row * E_))[threadIdx.x];
    float ss = a.x * a.x + a.y * a.y + a.z * a.z + a.w * a.w;
    __shared__ float red[8];
    __shared__ float sinv;
#pragma unroll
    for (int o = 16; o > 0; o >>= 1) ss += __shfl_xor_sync(0xffffffffu, ss, o);
    if ((threadIdx.x & 31) == 0) red[threadIdx.x >> 5] = ss;
    __syncthreads();
    if (threadIdx.x == 0) {
        float t = 0.f;
#pragma unroll
        for (int i = 0; i < 8; i++) t += red[i];
        sinv = rsqrtf(t * (1.0f / E_));
    }
    __syncthreads();
    float c = sinv;
    float4 o = make_float4(a.x * c, a.y * c, a.z * c, a.w * c);
    ((float4*)(y + (size_t)row * E_))[threadIdx.x] = o;
}

// ---------------- fused: x = x + rmsnorm(x);  h = rmsnorm(x) ----------------
__global__ __launch_bounds__(256) void addnorm_kernel(float* __restrict__ x,
                                                      float* __restrict__ h) {
    int row = blockIdx.x;
    float4 a = ((const float4*)(x + (size_t)row * E_))[threadIdx.x];
    __shared__ float red[8];
    __shared__ float sval;
    float ss = a.x * a.x + a.y * a.y + a.z * a.z + a.w * a.w;
#pragma unroll
    for (int o = 16; o > 0; o >>= 1) ss += __shfl_xor_sync(0xffffffffu, ss, o);
    if ((threadIdx.x & 31) == 0) red[threadIdx.x >> 5] = ss;
    __syncthreads();
    if (threadIdx.x == 0) {
        float t = 0.f;
#pragma unroll
        for (int i = 0; i < 8; i++) t += red[i];
        sval = 1.0f + rsqrtf(t * (1.0f / E_));
    }
    __syncthreads();
    float c = sval;
    a.x *= c; a.y *= c; a.z *= c; a.w *= c;
    float ss2 = a.x * a.x + a.y * a.y + a.z * a.z + a.w * a.w;
#pragma unroll
    for (int o = 16; o > 0; o >>= 1) ss2 += __shfl_xor_sync(0xffffffffu, ss2, o);
    if ((threadIdx.x & 31) == 0) red[threadIdx.x >> 5] = ss2;
    __syncthreads();
    if (threadIdx.x == 0) {
        float t = 0.f;
#pragma unroll
        for (int i = 0; i < 8; i++) t += red[i];
        sval = rsqrtf(t * (1.0f / E_));
    }
    __syncthreads();
    float inv2 = sval;
    ((float4*)(x + (size_t)row * E_))[threadIdx.x] = a;
    float4 o = make_float4(a.x * inv2, a.y * inv2, a.z * inv2, a.w * inv2);
    ((float4*)(h + (size_t)row * E_))[threadIdx.x] = o;
}

// ---------------- geglu ----------------
__global__ __launch_bounds__(256) void geglu_kernel(float* __restrict__ g,
                                                    const float* __restrict__ v) {
    int i = blockIdx.x * 256 + threadIdx.x;
    float x = g[i];
    float gel = 0.5f * x * (1.0f + erff(x * 0.70710678118654752f));
    g[i] = gel * v[i];
}

// ================= tf32 mma helpers =================
// NOTE: we feed raw fp32 bit patterns (no cvt.rna) — HW uses the tf32-significant
// bits (round-toward-zero). ~2x larger rounding error, far under the 1e-3 gate,
// and removes one ALU op + one 4-cycle dependency per fragment element.
__device__ __forceinline__ uint32_t f2r(float f) { return __float_as_uint(f); }

__device__ __forceinline__ void mma_tf32(float* d, const uint32_t* a, const uint32_t* b) {
    asm volatile(
        "mma.sync.aligned.m16n8k8.row.col.f32.tf32.tf32.f32 "
        "{%0,%1,%2,%3}, {%4,%5,%6,%7}, {%8,%9}, {%0,%1,%2,%3};\n"
        : "+f"(d[0]), "+f"(d[1]), "+f"(d[2]), "+f"(d[3])
        : "r"(a[0]), "r"(a[1]), "r"(a[2]), "r"(a[3]), "r"(b[0]), "r"(b[1]));
}

// ================= tf32 tensor-core GEMM =================
#define BM 128
#define BN 128
#define BK 32
#define APAD 4
#define BPAD 8
#define ASTRIDE (BK + APAD)           // 36
#define BSTRIDE (BN + BPAD)           // 136
#define TG_SMEM ((2 * BM * ASTRIDE + 2 * BK * BSTRIDE) * 4)  // 71680 B

// B2 != nullptr => dual-output mode: blockIdx.z selects (B,C) vs (B2,C2).
__global__ __launch_bounds__(256, 2) void tgemm_kernel(
    int M, int N, int K,
    const float* __restrict__ A, const float* __restrict__ B,
    const float* __restrict__ bias, const float* __restrict__ res,
    float* __restrict__ C,
    const float* __restrict__ B2, float* __restrict__ C2) {
    extern __shared__ float sm[];
    float* As = sm;
    float* Bs = sm + 2 * BM * ASTRIDE;

    if (B2 && blockIdx.z) { B = B2; C = C2; }

    const int tid  = threadIdx.x;
    const int bm   = blockIdx.y * BM;
    const int bn   = blockIdx.x * BN;
    const int warp = tid >> 5, lane = tid & 31;
    const int wm   = (warp >> 2) * 64;
    const int wn   = (warp & 3) * 32;
    const int fr   = lane >> 2;
    const int fc   = lane & 3;

    const int ar = tid >> 3;
    const int ac = (tid & 7) * 4;
    const int br = tid >> 5;
    const int bc = (tid & 31) * 4;

    float acc[4][4][4];
#pragma unroll
    for (int i = 0; i < 4; i++)
#pragma unroll
        for (int j = 0; j < 4; j++)
#pragma unroll
            for (int k = 0; k < 4; k++) acc[i][j][k] = 0.f;

    auto issue_loads = [&](int s, int kt) {
        float* Ad = As + s * BM * ASTRIDE;
        float* Bd = Bs + s * BK * BSTRIDE;
#pragma unroll
        for (int p = 0; p < 4; p++) {
            int row = p * 32 + ar;
            uint32_t dst = (uint32_t)__cvta_generic_to_shared(Ad + row * ASTRIDE + ac);
            const float* src = A + (size_t)(bm + row) * K + kt + ac;
            asm volatile("cp.async.cg.shared.global [%0], [%1], 16;\n" :: "r"(dst), "l"(src));
        }
#pragma unroll
        for (int p = 0; p < 4; p++) {
            int row = p * 8 + br;
            uint32_t dst = (uint32_t)__cvta_generic_to_shared(Bd + row * BSTRIDE + bc);
            const float* src = B + (size_t)(kt + row) * N + bn + bc;
            asm volatile("cp.async.cg.shared.global [%0], [%1], 16;\n" :: "r"(dst), "l"(src));
        }
        asm volatile("cp.async.commit_group;\n");
    };

    auto compute_tile = [&](int s) {
        const float* Ab = As + s * BM * ASTRIDE;
        const float* Bb = Bs + s * BK * BSTRIDE;
#pragma unroll
        for (int ks = 0; ks < 4; ks++) {
            const int k0 = ks * 8;
            uint32_t af[4][4], bf[4][2];
#pragma unroll
            for (int mi = 0; mi < 4; mi++) {
                int m = wm + mi * 16 + fr;
                af[mi][0] = f2r(Ab[m * ASTRIDE + k0 + fc]);
                af[mi][1] = f2r(Ab[(m + 8) * ASTRIDE + k0 + fc]);
                af[mi][2] = f2r(Ab[m * ASTRIDE + k0 + fc + 4]);
                af[mi][3] = f2r(Ab[(m + 8) * ASTRIDE + k0 + fc + 4]);
            }
#pragma unroll
            for (int ni = 0; ni < 4; ni++) {
                int n = wn + ni * 8 + fr;
                bf[ni][0] = f2r(Bb[(k0 + fc) * BSTRIDE + n]);
                bf[ni][1] = f2r(Bb[(k0 + fc + 4) * BSTRIDE + n]);
            }
#pragma unroll
            for (int mi = 0; mi < 4; mi++)
#pragma unroll
                for (int ni = 0; ni < 4; ni++) mma_tf32(acc[mi][ni], af[mi], bf[ni]);
        }
    };

    const int kiters = K / BK;
    issue_loads(0, 0);
    asm volatile("cp.async.wait_group 0;\n");
    __syncthreads();

#pragma unroll 1
    for (int it = 0; it < kiters; ++it) {
        int cur = it & 1;
        if (it + 1 < kiters) issue_loads(cur ^ 1, (it + 1) * BK);
        compute_tile(cur);
        asm volatile("cp.async.wait_group 0;\n");
        __syncthreads();
    }

#pragma unroll
    for (int mi = 0; mi < 4; mi++) {
#pragma unroll
        for (int ni = 0; ni < 4; ni++) {
            int gr = bm + wm + mi * 16 + fr;
            int gc = bn + wn + ni * 8 + fc * 2;
            float2 o0 = make_float2(acc[mi][ni][0], acc[mi][ni][1]);
            float2 o1 = make_float2(acc[mi][ni][2], acc[mi][ni][3]);
            if (bias) {
                float2 bv = *(const float2*)(bias + gc);
                o0.x += bv.x; o0.y += bv.y;
                o1.x += bv.x; o1.y += bv.y;
            }
            if (res) {
                float2 r0 = *(const float2*)(res + (size_t)gr * N + gc);
                float2 r1 = *(const float2*)(res + (size_t)(gr + 8) * N + gc);
                o0.x += r0.x; o0.y += r0.y;
                o1.x += r1.x; o1.y += r1.y;
            }
            *(float2*)(C + (size_t)gr * N + gc) = o0;
            *(float2*)(C + (size_t)(gr + 8) * N + gc) = o1;
        }
    }
}

// ================= tf32 tensor-core flash attention =================
#define PQ_STRIDE 68   // == 4 mod 32 -> conflict-free A-fragment reads
#define KV_STRIDE 72   // == 8 mod 32 -> conflict-free B-fragment reads
#define ATT_SMEM ((64 * PQ_STRIDE * 2 + 64 * KV_STRIDE * 2) * 4)  // 71680 B

__global__ __launch_bounds__(128) void attn_kernel(const float* __restrict__ qkv,
                                                   float* __restrict__ ctx) {
    extern __shared__ float smr[];
    float* Qs = smr;                         // [64][68]
    float* Ps = Qs + 64 * PQ_STRIDE;         // [64][68]
    float* Ks = Ps + 64 * PQ_STRIDE;         // [64(d)][72(key)]  (transposed)
    float* Vs = Ks + 64 * KV_STRIDE;         // [64(key)][72(d)]

    const int qt = blockIdx.x, h = blockIdx.y, b = blockIdx.z;
    const int m0 = qt * 64;
    const int tid  = threadIdx.x;
    const int warp = tid >> 5, lane = tid & 31;
    const int fr = lane >> 2, fc = lane & 3;
    const int w16 = warp * 16;
    const float slope = exp2f(-(1.0f + 7.0f * (float)h / 15.0f));

    for (int i = tid; i < 64 * 16; i += 128) {
        int r = i >> 4, c = (i & 15) << 2;
        float4 v = *(const float4*)(qkv + ((((size_t)(b * L_ + m0 + r) * H_ + h) * 3 + 0) * D_ + c));
        Qs[r * PQ_STRIDE + c + 0] = v.x * 0.125f;
        Qs[r * PQ_STRIDE + c + 1] = v.y * 0.125f;
        Qs[r * PQ_STRIDE + c + 2] = v.z * 0.125f;
        Qs[r * PQ_STRIDE + c + 3] = v.w * 0.125f;
    }
    __syncthreads();

    uint32_t qf[8][4];
#pragma unroll
    for (int ks = 0; ks < 8; ks++) {
        int k0 = ks * 8;
        qf[ks][0] = f2r(Qs[(w16 + fr) * PQ_STRIDE + k0 + fc]);
        qf[ks][1] = f2r(Qs[(w16 + fr + 8) * PQ_STRIDE + k0 + fc]);
        qf[ks][2] = f2r(Qs[(w16 + fr) * PQ_STRIDE + k0 + fc + 4]);
        qf[ks][3] = f2r(Qs[(w16 + fr + 8) * PQ_STRIDE + k0 + fc + 4]);
    }

    float oacc[8][4];
#pragma unroll
    for (int i = 0; i < 8; i++)
#pragma unroll
        for (int j = 0; j < 4; j++) oacc[i][j] = 0.f;
    float mrow0 = -CUDART_INF_F, mrow1 = -CUDART_INF_F;
    float lrow0 = 0.f, lrow1 = 0.f;

    const int gi0 = m0 + w16 + fr;
    const int gi1 = gi0 + 8;

    for (int kt = 0; kt <= qt; kt++) {
        const int n0 = kt * 64;
        __syncthreads();
        for (int i = tid; i < 64 * 16; i += 128) {
            int r = i >> 4, c = (i & 15) << 2;
            size_t base = ((size_t)(b * L_ + n0 + r) * H_ + h) * 3;
            float4 kv = *(const float4*)(qkv + (base + 1) * D_ + c);
            float4 vv = *(const float4*)(qkv + (base + 2) * D_ + c);
            Ks[(c + 0) * KV_STRIDE + r] = kv.x;
            Ks[(c + 1) * KV_STRIDE + r] = kv.y;
            Ks[(c + 2) * KV_STRIDE + r] = kv.z;
            Ks[(c + 3) * KV_STRIDE + r] = kv.w;
            Vs[r * KV_STRIDE + c + 0] = vv.x;
            Vs[r * KV_STRIDE + c + 1] = vv.y;
            Vs[r * KV_STRIDE + c + 2] = vv.z;
            Vs[r * KV_STRIDE + c + 3] = vv.w;
        }
        __syncthreads();

        float sacc[8][4];
#pragma unroll
        for (int i = 0; i < 8; i++)
#pragma unroll
            for (int j = 0; j < 4; j++) sacc[i][j] = 0.f;
#pragma unroll
        for (int ks = 0; ks < 8; ks++) {
            int k0 = ks * 8;
            uint32_t bf[8][2];
#pragma unroll
            for (int ni = 0; ni < 8; ni++) {
                int n = ni * 8 + fr;
                bf[ni][0] = f2r(Ks[(k0 + fc) * KV_STRIDE + n]);
                bf[ni][1] = f2r(Ks[(k0 + fc + 4) * KV_STRIDE + n]);
            }
#pragma unroll
            for (int ni = 0; ni < 8; ni++) mma_tf32(sacc[ni], qf[ks], bf[ni]);
        }

#pragma unroll
        for (int ni = 0; ni < 8; ni++) {
            int gj = n0 + ni * 8 + 2 * fc;
            float a0 = slope * (float)(gj - gi0);
            float a1 = slope * (float)(gj + 1 - gi0);
            float a2 = slope * (float)(gj - gi1);
            float a3 = slope * (float)(gj + 1 - gi1);
            sacc[ni][0] = (gj     > gi0) ? -CUDART_INF_F : sacc[ni][0] + a0;
            sacc[ni][1] = (gj + 1 > gi0) ? -CUDART_INF_F : sacc[ni][1] + a1;
            sacc[ni][2] = (gj     > gi1) ? -CUDART_INF_F : sacc[ni][2] + a2;
            sacc[ni][3] = (gj + 1 > gi1) ? -CUDART_INF_F : sacc[ni][3] + a3;
        }

        float mx0 = -CUDART_INF_F, mx1 = -CUDART_INF_F;
#pragma unroll
        for (int ni = 0; ni < 8; ni++) {
            mx0 = fmaxf(mx0, fmaxf(sacc[ni][0], sacc[ni][1]));
            mx1 = fmaxf(mx1, fmaxf(sacc[ni][2], sacc[ni][3]));
        }
        mx0 = fmaxf(mx0, __shfl_xor_sync(0xffffffffu, mx0, 1));
        mx0 = fmaxf(mx0, __shfl_xor_sync(0xffffffffu, mx0, 2));
        mx1 = fmaxf(mx1, __shfl_xor_sync(0xffffffffu, mx1, 1));
        mx1 = fmaxf(mx1, __shfl_xor_sync(0xffffffffu, mx1, 2));
        float mn0 = fmaxf(mrow0, mx0);
        float mn1 = fmaxf(mrow1, mx1);
        float alpha0 = __expf(mrow0 - mn0);
        float alpha1 = __expf(mrow1 - mn1);
        float rs0 = 0.f, rs1 = 0.f;
#pragma unroll
        for (int ni = 0; ni < 8; ni++) {
            sacc[ni][0] = __expf(sacc[ni][0] - mn0);
            sacc[ni][1] = __expf(sacc[ni][1] - mn0);
            sacc[ni][2] = __expf(sacc[ni][2] - mn1);
            sacc[ni][3] = __expf(sacc[ni][3] - mn1);
            rs0 += sacc[ni][0] + sacc[ni][1];
            rs1 += sacc[ni][2] + sacc[ni][3];
        }
        rs0 += __shfl_xor_sync(0xffffffffu, rs0, 1);
        rs0 += __shfl_xor_sync(0xffffffffu, rs0, 2);
        rs1 += __shfl_xor_sync(0xffffffffu, rs1, 1);
        rs1 += __shfl_xor_sync(0xffffffffu, rs1, 2);
        lrow0 = lrow0 * alpha0 + rs0;
        lrow1 = lrow1 * alpha1 + rs1;
        mrow0 = mn0;
        mrow1 = mn1;
#pragma unroll
        for (int ni = 0; ni < 8; ni++) {
            oacc[ni][0] *= alpha0;
            oacc[ni][1] *= alpha0;
            oacc[ni][2] *= alpha1;
            oacc[ni][3] *= alpha1;
        }

#pragma unroll
        for (int ni = 0; ni < 8; ni++) {
            int c = ni * 8 + 2 * fc;
            *(float2*)&Ps[(w16 + fr) * PQ_STRIDE + c]     = make_float2(sacc[ni][0], sacc[ni][1]);
            *(float2*)&Ps[(w16 + fr + 8) * PQ_STRIDE + c] = make_float2(sacc[ni][2], sacc[ni][3]);
        }
        __syncwarp();

#pragma unroll
        for (int ks = 0; ks < 8; ks++) {
            int k0 = ks * 8;
            uint32_t af[4];
            af[0] = f2r(Ps[(w16 + fr) * PQ_STRIDE + k0 + fc]);
            af[1] = f2r(Ps[(w16 + fr + 8) * PQ_STRIDE + k0 + fc]);
            af[2] = f2r(Ps[(w16 + fr) * PQ_STRIDE + k0 + fc + 4]);
            af[3] = f2r(Ps[(w16 + fr + 8) * PQ_STRIDE + k0 + fc + 4]);
#pragma unroll
            for (int ni = 0; ni < 8; ni++) {
                uint32_t bf[2];
                int n = ni * 8 + fr;
                bf[0] = f2r(Vs[(k0 + fc) * KV_STRIDE + n]);
                bf[1] = f2r(Vs[(k0 + fc + 4) * KV_STRIDE + n]);
                mma_tf32(oacc[ni], af, bf);
            }
        }
        __syncwarp();
    }

    float inv0 = 1.0f / lrow0;
    float inv1 = 1.0f / lrow1;
#pragma unroll
    for (int ni = 0; ni < 8; ni++) {
        int c = h * D_ + ni * 8 + 2 * fc;
        *(float2*)(ctx + (size_t)(b * L_ + gi0) * (H_ * D_) + c) =
            make_float2(oacc[ni][0] * inv0, oacc[ni][1] * inv0);
        *(float2*)(ctx + (size_t)(b * L_ + gi1) * (H_ * D_) + c) =
            make_float2(oacc[ni][2] * inv1, oacc[ni][3] * inv1);
    }
}

// ---------------- launch ----------------
extern "C" void kernel_launch(void* const* d_in, const int* in_sizes, int n_in,
                              void* d_out, int out_size) {
    (void)in_sizes; (void)n_in; (void)out_size;
    const float* X    = (const float*)d_in[0];
    const float* Wqkv = (const float*)d_in[2];
    const float* bqkv = (const float*)d_in[3];
    const float* Wo   = (const float*)d_in[4];
    const float* bo   = (const float*)d_in[5];
    const float* Ww   = (const float*)d_in[12];
    const float* Wv   = (const float*)d_in[13];
    const float* Wout = (const float*)d_in[14];
    float* out = (float*)d_out;

    float *h_p, *qkv_p, *ctx_p, *x_p, *g_p, *v_p;
    cudaGetSymbolAddress((void**)&h_p,   g_h);
    cudaGetSymbolAddress((void**)&qkv_p, g_qkv);
    cudaGetSymbolAddress((void**)&ctx_p, g_ctx);
    cudaGetSymbolAddress((void**)&x_p,   g_x);
    cudaGetSymbolAddress((void**)&g_p,   g_gate);
    cudaGetSymbolAddress((void**)&v_p,   g_val);

    cudaFuncSetAttribute(attn_kernel, cudaFuncAttributeMaxDynamicSharedMemorySize, ATT_SMEM);
    cudaFuncSetAttribute(tgemm_kernel, cudaFuncAttributeMaxDynamicSharedMemorySize, TG_SMEM);

    // 1. h = rmsnorm(X)
    rmsnorm_kernel<<<M_, 256>>>(X, h_p);
    // 2. qkv = h @ Wqkv + bqkv
    tgemm_kernel<<<dim3(3 * H_ * D_ / BN, M_ / BM), 256, TG_SMEM>>>(
        M_, 3 * H_ * D_, E_, h_p, Wqkv, bqkv, nullptr, qkv_p, nullptr, nullptr);
    // 3. attention (tf32 mma flash)
    attn_kernel<<<dim3(L_ / 64, H_, B_), 128, ATT_SMEM>>>(qkv_p, ctx_p);
    // 4. x = X + ctx @ Wo + bo
    tgemm_kernel<<<dim3(E_ / BN, M_ / BM), 256, TG_SMEM>>>(
        M_, E_, H_ * D_, ctx_p, Wo, bo, X, x_p, nullptr, nullptr);
    // 5+6. x = x + rmsnorm(x); h = rmsnorm(x)
    addnorm_kernel<<<M_, 256>>>(x_p, h_p);
    // 7. gate = h @ Ww ; val = h @ Wv  (single dual-output launch, z selects)
    tgemm_kernel<<<dim3(DFF_ / BN, M_ / BM, 2), 256, TG_SMEM>>>(
        M_, DFF_, E_, h_p, Ww, nullptr, nullptr, g_p, Wv, v_p);
    // 8. gate = gelu(gate) * val
    geglu_kernel<<<(M_ * DFF_) / 256, 256>>>(g_p, v_p);
    // 9. out = x + gate @ Wout
    tgemm_kernel<<<dim3(E_ / BN, M_ / BM), 256, TG_SMEM>>>(
        M_, E_, DFF_, g_p, Wout, nullptr, x_p, out, nullptr, nullptr);
}

// round 5
// speedup vs baseline: 3.8125x; 1.0490x over previous
#include <cuda_runtime.h>
#include <math_constants.h>
#include <cstdint>

#define B_   2
#define L_   2048
#define E_   1024
#define H_   16
#define D_   64
#define DFF_ 4096
#define M_   (B_ * L_)   // 4096 tokens

// ---------------- scratch (device globals: allocation-guard safe) ----------------
__device__ float g_h[M_ * E_];
__device__ float g_qkv[(size_t)M_ * 3 * H_ * D_];
__device__ float g_ctx[M_ * H_ * D_];
__device__ float g_x[M_ * E_];
__device__ float g_gate[(size_t)M_ * DFF_];
__device__ float g_val[(size_t)M_ * DFF_];

// ---------------- rmsnorm ----------------
__global__ __launch_bounds__(256) void rmsnorm_kernel(const float* __restrict__ x,
                                                      float* __restrict__ y) {
    int row = blockIdx.x;
    float4 a = ((const float4*)(x + (size_t)row * E_))[threadIdx.x];
    float ss = a.x * a.x + a.y * a.y + a.z * a.z + a.w * a.w;
    __shared__ float red[8];
    __shared__ float sinv;
#pragma unroll
    for (int o = 16; o > 0; o >>= 1) ss += __shfl_xor_sync(0xffffffffu, ss, o);
    if ((threadIdx.x & 31) == 0) red[threadIdx.x >> 5] = ss;
    __syncthreads();
    if (threadIdx.x == 0) {
        float t = 0.f;
#pragma unroll
        for (int i = 0; i < 8; i++) t += red[i];
        sinv = rsqrtf(t * (1.0f / E_));
    }
    __syncthreads();
    float c = sinv;
    float4 o = make_float4(a.x * c, a.y * c, a.z * c, a.w * c);
    ((float4*)(y + (size_t)row * E_))[threadIdx.x] = o;
}

// ---------------- fused: x = x + rmsnorm(x);  h = rmsnorm(x) ----------------
__global__ __launch_bounds__(256) void addnorm_kernel(float* __restrict__ x,
                                                      float* __restrict__ h) {
    int row = blockIdx.x;
    float4 a = ((const float4*)(x + (size_t)row * E_))[threadIdx.x];
    __shared__ float red[8];
    __shared__ float sval;
    float ss = a.x * a.x + a.y * a.y + a.z * a.z + a.w * a.w;
#pragma unroll
    for (int o = 16; o > 0; o >>= 1) ss += __shfl_xor_sync(0xffffffffu, ss, o);
    if ((threadIdx.x & 31) == 0) red[threadIdx.x >> 5] = ss;
    __syncthreads();
    if (threadIdx.x == 0) {
        float t = 0.f;
#pragma unroll
        for (int i = 0; i < 8; i++) t += red[i];
        sval = 1.0f + rsqrtf(t * (1.0f / E_));
    }
    __syncthreads();
    float c = sval;
    a.x *= c; a.y *= c; a.z *= c; a.w *= c;
    float ss2 = a.x * a.x + a.y * a.y + a.z * a.z + a.w * a.w;
#pragma unroll
    for (int o = 16; o > 0; o >>= 1) ss2 += __shfl_xor_sync(0xffffffffu, ss2, o);
    if ((threadIdx.x & 31) == 0) red[threadIdx.x >> 5] = ss2;
    __syncthreads();
    if (threadIdx.x == 0) {
        float t = 0.f;
#pragma unroll
        for (int i = 0; i < 8; i++) t += red[i];
        sval = rsqrtf(t * (1.0f / E_));
    }
    __syncthreads();
    float inv2 = sval;
    ((float4*)(x + (size_t)row * E_))[threadIdx.x] = a;
    float4 o = make_float4(a.x * inv2, a.y * inv2, a.z * inv2, a.w * inv2);
    ((float4*)(h + (size_t)row * E_))[threadIdx.x] = o;
}

// ---------------- geglu ----------------
__global__ __launch_bounds__(256) void geglu_kernel(float* __restrict__ g,
                                                    const float* __restrict__ v) {
    int i = blockIdx.x * 256 + threadIdx.x;
    float x = g[i];
    float gel = 0.5f * x * (1.0f + erff(x * 0.70710678118654752f));
    g[i] = gel * v[i];
}

// ================= tf32 mma helpers =================
__device__ __forceinline__ uint32_t f2r(float f) { return __float_as_uint(f); }

__device__ __forceinline__ void mma_tf32(float* d, const uint32_t* a, const uint32_t* b) {
    asm volatile(
        "mma.sync.aligned.m16n8k8.row.col.f32.tf32.tf32.f32 "
        "{%0,%1,%2,%3}, {%4,%5,%6,%7}, {%8,%9}, {%0,%1,%2,%3};\n"
        : "+f"(d[0]), "+f"(d[1]), "+f"(d[2]), "+f"(d[3])
        : "r"(a[0]), "r"(a[1]), "r"(a[2]), "r"(a[3]), "r"(b[0]), "r"(b[1]));
}

// ldmatrix.x4: 4x (8 rows x 16B). With lanes 0-7 -> rows of tile0 (m..m+7, k0),
// 8-15 -> tile1 (m+8.., k0), 16-23 -> tile2 (m.., k0+4), 24-31 -> tile3 (m+8.., k0+4)
// this yields exactly the tf32 m16n8k8 A fragment {a0,a1,a2,a3}.
__device__ __forceinline__ void ldsm4(uint32_t* r, uint32_t saddr) {
    asm volatile("ldmatrix.sync.aligned.m8n8.x4.shared.b16 {%0,%1,%2,%3}, [%4];"
                 : "=r"(r[0]), "=r"(r[1]), "=r"(r[2]), "=r"(r[3]) : "r"(saddr));
}

// ================= tf32 tensor-core GEMM =================
#define BM 128
#define BN 128
#define BK 32
#define APAD 4
#define BPAD 8
#define ASTRIDE (BK + APAD)           // 36 floats = 144B rows (16B aligned)
#define BSTRIDE (BN + BPAD)           // 136
#define TG_SMEM ((2 * BM * ASTRIDE + 2 * BK * BSTRIDE) * 4)  // 71680 B

// B2 != nullptr => dual-output mode: blockIdx.z selects (B,C) vs (B2,C2).
__global__ __launch_bounds__(256, 2) void tgemm_kernel(
    int M, int N, int K,
    const float* __restrict__ A, const float* __restrict__ B,
    const float* __restrict__ bias, const float* __restrict__ res,
    float* __restrict__ C,
    const float* __restrict__ B2, float* __restrict__ C2) {
    extern __shared__ float sm[];
    float* As = sm;
    float* Bs = sm + 2 * BM * ASTRIDE;

    if (B2 && blockIdx.z) { B = B2; C = C2; }

    const int tid  = threadIdx.x;
    const int bm   = blockIdx.y * BM;
    const int bn   = blockIdx.x * BN;
    const int warp = tid >> 5, lane = tid & 31;
    const int wm   = (warp >> 2) * 64;
    const int wn   = (warp & 3) * 32;
    const int fr   = lane >> 2;
    const int fc   = lane & 3;

    // ldmatrix per-lane source row/col within a 16x8 fragment tile
    const int lg   = lane >> 3;                  // matrix id 0..3
    const int lrow = ((lg & 1) << 3) + (lane & 7);
    const int lcol = (lg >> 1) << 2;

    const int ar = tid >> 3;
    const int ac = (tid & 7) * 4;
    const int br = tid >> 5;
    const int bc = (tid & 31) * 4;

    float acc[4][4][4];
#pragma unroll
    for (int i = 0; i < 4; i++)
#pragma unroll
        for (int j = 0; j < 4; j++)
#pragma unroll
            for (int k = 0; k < 4; k++) acc[i][j][k] = 0.f;

    auto issue_loads = [&](int s, int kt) {
        float* Ad = As + s * BM * ASTRIDE;
        float* Bd = Bs + s * BK * BSTRIDE;
#pragma unroll
        for (int p = 0; p < 4; p++) {
            int row = p * 32 + ar;
            uint32_t dst = (uint32_t)__cvta_generic_to_shared(Ad + row * ASTRIDE + ac);
            const float* src = A + (size_t)(bm + row) * K + kt + ac;
            asm volatile("cp.async.cg.shared.global [%0], [%1], 16;\n" :: "r"(dst), "l"(src));
        }
#pragma unroll
        for (int p = 0; p < 4; p++) {
            int row = p * 8 + br;
            uint32_t dst = (uint32_t)__cvta_generic_to_shared(Bd + row * BSTRIDE + bc);
            const float* src = B + (size_t)(kt + row) * N + bn + bc;
            asm volatile("cp.async.cg.shared.global [%0], [%1], 16;\n" :: "r"(dst), "l"(src));
        }
        asm volatile("cp.async.commit_group;\n");
    };

    auto compute_tile = [&](int s) {
        const float* Ab = As + s * BM * ASTRIDE;
        const float* Bb = Bs + s * BK * BSTRIDE;
        // per-lane ldmatrix base (row part fixed, col varies with ks)
        uint32_t abase = (uint32_t)__cvta_generic_to_shared(Ab + (wm + lrow) * ASTRIDE + lcol);
#pragma unroll
        for (int ks = 0; ks < 4; ks++) {
            const int k0 = ks * 8;
            uint32_t af[4][4], bf[4][2];
#pragma unroll
            for (int mi = 0; mi < 4; mi++)
                ldsm4(af[mi], abase + (mi * 16 * ASTRIDE + k0) * 4);
#pragma unroll
            for (int ni = 0; ni < 4; ni++) {
                int n = wn + ni * 8 + fr;
                bf[ni][0] = f2r(Bb[(k0 + fc) * BSTRIDE + n]);
                bf[ni][1] = f2r(Bb[(k0 + fc + 4) * BSTRIDE + n]);
            }
#pragma unroll
            for (int mi = 0; mi < 4; mi++)
#pragma unroll
                for (int ni = 0; ni < 4; ni++) mma_tf32(acc[mi][ni], af[mi], bf[ni]);
        }
    };

    const int kiters = K / BK;
    issue_loads(0, 0);
    asm volatile("cp.async.wait_group 0;\n");
    __syncthreads();

#pragma unroll 1
    for (int it = 0; it < kiters; ++it) {
        int cur = it & 1;
        if (it + 1 < kiters) issue_loads(cur ^ 1, (it + 1) * BK);
        compute_tile(cur);
        asm volatile("cp.async.wait_group 0;\n");
        __syncthreads();
    }

#pragma unroll
    for (int mi = 0; mi < 4; mi++) {
#pragma unroll
        for (int ni = 0; ni < 4; ni++) {
            int gr = bm + wm + mi * 16 + fr;
            int gc = bn + wn + ni * 8 + fc * 2;
            float2 o0 = make_float2(acc[mi][ni][0], acc[mi][ni][1]);
            float2 o1 = make_float2(acc[mi][ni][2], acc[mi][ni][3]);
            if (bias) {
                float2 bv = *(const float2*)(bias + gc);
                o0.x += bv.x; o0.y += bv.y;
                o1.x += bv.x; o1.y += bv.y;
            }
            if (res) {
                float2 r0 = *(const float2*)(res + (size_t)gr * N + gc);
                float2 r1 = *(const float2*)(res + (size_t)(gr + 8) * N + gc);
                o0.x += r0.x; o0.y += r0.y;
                o1.x += r1.x; o1.y += r1.y;
            }
            *(float2*)(C + (size_t)gr * N + gc) = o0;
            *(float2*)(C + (size_t)(gr + 8) * N + gc) = o1;
        }
    }
}

// ================= tf32 tensor-core flash attention =================
#define PQ_STRIDE 68   // == 4 mod 32 -> conflict-free A-fragment/LDSM reads
#define KV_STRIDE 72   // == 8 mod 32 -> conflict-free B-fragment reads
#define ATT_SMEM ((64 * PQ_STRIDE * 2 + 64 * KV_STRIDE * 2) * 4)  // 71680 B

__global__ __launch_bounds__(128) void attn_kernel(const float* __restrict__ qkv,
                                                   float* __restrict__ ctx) {
    extern __shared__ float smr[];
    float* Qs = smr;                         // [64][68]
    float* Ps = Qs + 64 * PQ_STRIDE;         // [64][68]
    float* Ks = Ps + 64 * PQ_STRIDE;         // [64(d)][72(key)]  (transposed)
    float* Vs = Ks + 64 * KV_STRIDE;         // [64(key)][72(d)]

    const int qt = blockIdx.x, h = blockIdx.y, b = blockIdx.z;
    const int m0 = qt * 64;
    const int tid  = threadIdx.x;
    const int warp = tid >> 5, lane = tid & 31;
    const int fr = lane >> 2, fc = lane & 3;
    const int w16 = warp * 16;
    const int lg   = lane >> 3;
    const int lrow = ((lg & 1) << 3) + (lane & 7);
    const int lcol = (lg >> 1) << 2;
    const float slope = exp2f(-(1.0f + 7.0f * (float)h / 15.0f));

    for (int i = tid; i < 64 * 16; i += 128) {
        int r = i >> 4, c = (i & 15) << 2;
        float4 v = *(const float4*)(qkv + ((((size_t)(b * L_ + m0 + r) * H_ + h) * 3 + 0) * D_ + c));
        Qs[r * PQ_STRIDE + c + 0] = v.x * 0.125f;
        Qs[r * PQ_STRIDE + c + 1] = v.y * 0.125f;
        Qs[r * PQ_STRIDE + c + 2] = v.z * 0.125f;
        Qs[r * PQ_STRIDE + c + 3] = v.w * 0.125f;
    }
    __syncthreads();

    const uint32_t qbase = (uint32_t)__cvta_generic_to_shared(Qs + (w16 + lrow) * PQ_STRIDE + lcol);
    const uint32_t pbase = (uint32_t)__cvta_generic_to_shared(Ps + (w16 + lrow) * PQ_STRIDE + lcol);

    uint32_t qf[8][4];
#pragma unroll
    for (int ks = 0; ks < 8; ks++) ldsm4(qf[ks], qbase + ks * 8 * 4);

    float oacc[8][4];
#pragma unroll
    for (int i = 0; i < 8; i++)
#pragma unroll
        for (int j = 0; j < 4; j++) oacc[i][j] = 0.f;
    float mrow0 = -CUDART_INF_F, mrow1 = -CUDART_INF_F;
    float lrow0 = 0.f, lrow1 = 0.f;

    const int gi0 = m0 + w16 + fr;
    const int gi1 = gi0 + 8;

    for (int kt = 0; kt <= qt; kt++) {
        const int n0 = kt * 64;
        __syncthreads();
        for (int i = tid; i < 64 * 16; i += 128) {
            int r = i >> 4, c = (i & 15) << 2;
            size_t base = ((size_t)(b * L_ + n0 + r) * H_ + h) * 3;
            float4 kv = *(const float4*)(qkv + (base + 1) * D_ + c);
            float4 vv = *(const float4*)(qkv + (base + 2) * D_ + c);
            Ks[(c + 0) * KV_STRIDE + r] = kv.x;
            Ks[(c + 1) * KV_STRIDE + r] = kv.y;
            Ks[(c + 2) * KV_STRIDE + r] = kv.z;
            Ks[(c + 3) * KV_STRIDE + r] = kv.w;
            Vs[r * KV_STRIDE + c + 0] = vv.x;
            Vs[r * KV_STRIDE + c + 1] = vv.y;
            Vs[r * KV_STRIDE + c + 2] = vv.z;
            Vs[r * KV_STRIDE + c + 3] = vv.w;
        }
        __syncthreads();

        float sacc[8][4];
#pragma unroll
        for (int i = 0; i < 8; i++)
#pragma unroll
            for (int j = 0; j < 4; j++) sacc[i][j] = 0.f;
#pragma unroll
        for (int ks = 0; ks < 8; ks++) {
            int k0 = ks * 8;
            uint32_t bf[8][2];
#pragma unroll
            for (int ni = 0; ni < 8; ni++) {
                int n = ni * 8 + fr;
                bf[ni][0] = f2r(Ks[(k0 + fc) * KV_STRIDE + n]);
                bf[ni][1] = f2r(Ks[(k0 + fc + 4) * KV_STRIDE + n]);
            }
#pragma unroll
            for (int ni = 0; ni < 8; ni++) mma_tf32(sacc[ni], qf[ks], bf[ni]);
        }

#pragma unroll
        for (int ni = 0; ni < 8; ni++) {
            int gj = n0 + ni * 8 + 2 * fc;
            float a0 = slope * (float)(gj - gi0);
            float a1 = slope * (float)(gj + 1 - gi0);
            float a2 = slope * (float)(gj - gi1);
            float a3 = slope * (float)(gj + 1 - gi1);
            sacc[ni][0] = (gj     > gi0) ? -CUDART_INF_F : sacc[ni][0] + a0;
            sacc[ni][1] = (gj + 1 > gi0) ? -CUDART_INF_F : sacc[ni][1] + a1;
            sacc[ni][2] = (gj     > gi1) ? -CUDART_INF_F : sacc[ni][2] + a2;
            sacc[ni][3] = (gj + 1 > gi1) ? -CUDART_INF_F : sacc[ni][3] + a3;
        }

        float mx0 = -CUDART_INF_F, mx1 = -CUDART_INF_F;
#pragma unroll
        for (int ni = 0; ni < 8; ni++) {
            mx0 = fmaxf(mx0, fmaxf(sacc[ni][0], sacc[ni][1]));
            mx1 = fmaxf(mx1, fmaxf(sacc[ni][2], sacc[ni][3]));
        }
        mx0 = fmaxf(mx0, __shfl_xor_sync(0xffffffffu, mx0, 1));
        mx0 = fmaxf(mx0, __shfl_xor_sync(0xffffffffu, mx0, 2));
        mx1 = fmaxf(mx1, __shfl_xor_sync(0xffffffffu, mx1, 1));
        mx1 = fmaxf(mx1, __shfl_xor_sync(0xffffffffu, mx1, 2));
        float mn0 = fmaxf(mrow0, mx0);
        float mn1 = fmaxf(mrow1, mx1);
        float alpha0 = __expf(mrow0 - mn0);
        float alpha1 = __expf(mrow1 - mn1);
        float rs0 = 0.f, rs1 = 0.f;
#pragma unroll
        for (int ni = 0; ni < 8; ni++) {
            sacc[ni][0] = __expf(sacc[ni][0] - mn0);
            sacc[ni][1] = __expf(sacc[ni][1] - mn0);
            sacc[ni][2] = __expf(sacc[ni][2] - mn1);
            sacc[ni][3] = __expf(sacc[ni][3] - mn1);
            rs0 += sacc[ni][0] + sacc[ni][1];
            rs1 += sacc[ni][2] + sacc[ni][3];
        }
        rs0 += __shfl_xor_sync(0xffffffffu, rs0, 1);
        rs0 += __shfl_xor_sync(0xffffffffu, rs0, 2);
        rs1 += __shfl_xor_sync(0xffffffffu, rs1, 1);
        rs1 += __shfl_xor_sync(0xffffffffu, rs1, 2);
        lrow0 = lrow0 * alpha0 + rs0;
        lrow1 = lrow1 * alpha1 + rs1;
        mrow0 = mn0;
        mrow1 = mn1;
#pragma unroll
        for (int ni = 0; ni < 8; ni++) {
            oacc[ni][0] *= alpha0;
            oacc[ni][1] *= alpha0;
            oacc[ni][2] *= alpha1;
            oacc[ni][3] *= alpha1;
        }

#pragma unroll
        for (int ni = 0; ni < 8; ni++) {
            int c = ni * 8 + 2 * fc;
            *(float2*)&Ps[(w16 + fr) * PQ_STRIDE + c]     = make_float2(sacc[ni][0], sacc[ni][1]);
            *(float2*)&Ps[(w16 + fr + 8) * PQ_STRIDE + c] = make_float2(sacc[ni][2], sacc[ni][3]);
        }
        __syncwarp();

#pragma unroll
        for (int ks = 0; ks < 8; ks++) {
            int k0 = ks * 8;
            uint32_t af[4];
            ldsm4(af, pbase + k0 * 4);
#pragma unroll
            for (int ni = 0; ni < 8; ni++) {
                uint32_t bf[2];
                int n = ni * 8 + fr;
                bf[0] = f2r(Vs[(k0 + fc) * KV_STRIDE + n]);
                bf[1] = f2r(Vs[(k0 + fc + 4) * KV_STRIDE + n]);
                mma_tf32(oacc[ni], af, bf);
            }
        }
        __syncwarp();
    }

    float inv0 = 1.0f / lrow0;
    float inv1 = 1.0f / lrow1;
#pragma unroll
    for (int ni = 0; ni < 8; ni++) {
        int c = h * D_ + ni * 8 + 2 * fc;
        *(float2*)(ctx + (size_t)(b * L_ + gi0) * (H_ * D_) + c) =
            make_float2(oacc[ni][0] * inv0, oacc[ni][1] * inv0);
        *(float2*)(ctx + (size_t)(b * L_ + gi1) * (H_ * D_) + c) =
            make_float2(oacc[ni][2] * inv1, oacc[ni][3] * inv1);
    }
}

// ---------------- launch ----------------
extern "C" void kernel_launch(void* const* d_in, const int* in_sizes, int n_in,
                              void* d_out, int out_size) {
    (void)in_sizes; (void)n_in; (void)out_size;
    const float* X    = (const float*)d_in[0];
    const float* Wqkv = (const float*)d_in[2];
    const float* bqkv = (const float*)d_in[3];
    const float* Wo   = (const float*)d_in[4];
    const float* bo   = (const float*)d_in[5];
    const float* Ww   = (const float*)d_in[12];
    const float* Wv   = (const float*)d_in[13];
    const float* Wout = (const float*)d_in[14];
    float* out = (float*)d_out;

    float *h_p, *qkv_p, *ctx_p, *x_p, *g_p, *v_p;
    cudaGetSymbolAddress((void**)&h_p,   g_h);
    cudaGetSymbolAddress((void**)&qkv_p, g_qkv);
    cudaGetSymbolAddress((void**)&ctx_p, g_ctx);
    cudaGetSymbolAddress((void**)&x_p,   g_x);
    cudaGetSymbolAddress((void**)&g_p,   g_gate);
    cudaGetSymbolAddress((void**)&v_p,   g_val);

    cudaFuncSetAttribute(attn_kernel, cudaFuncAttributeMaxDynamicSharedMemorySize, ATT_SMEM);
    cudaFuncSetAttribute(tgemm_kernel, cudaFuncAttributeMaxDynamicSharedMemorySize, TG_SMEM);

    // 1. h = rmsnorm(X)
    rmsnorm_kernel<<<M_, 256>>>(X, h_p);
    // 2. qkv = h @ Wqkv + bqkv
    tgemm_kernel<<<dim3(3 * H_ * D_ / BN, M_ / BM), 256, TG_SMEM>>>(
        M_, 3 * H_ * D_, E_, h_p, Wqkv, bqkv, nullptr, qkv_p, nullptr, nullptr);
    // 3. attention (tf32 mma flash)
    attn_kernel<<<dim3(L_ / 64, H_, B_), 128, ATT_SMEM>>>(qkv_p, ctx_p);
    // 4. x = X + ctx @ Wo + bo
    tgemm_kernel<<<dim3(E_ / BN, M_ / BM), 256, TG_SMEM>>>(
        M_, E_, H_ * D_, ctx_p, Wo, bo, X, x_p, nullptr, nullptr);
    // 5+6. x = x + rmsnorm(x); h = rmsnorm(x)
    addnorm_kernel<<<M_, 256>>>(x_p, h_p);
    // 7. gate = h @ Ww ; val = h @ Wv  (single dual-output launch, z selects)
    tgemm_kernel<<<dim3(DFF_ / BN, M_ / BM, 2), 256, TG_SMEM>>>(
        M_, DFF_, E_, h_p, Ww, nullptr, nullptr, g_p, Wv, v_p);
    // 8. gate = gelu(gate) * val
    geglu_kernel<<<(M_ * DFF_) / 256, 256>>>(g_p, v_p);
    // 9. out = x + gate @ Wout
    tgemm_kernel<<<dim3(E_ / BN, M_ / BM), 256, TG_SMEM>>>(
        M_, E_, DFF_, g_p, Wout, nullptr, x_p, out, nullptr, nullptr);
}